// round 1
// baseline (speedup 1.0000x reference)
#include <cuda_runtime.h>
#include <math.h>

// GAT forward_user, fully fused flash-style:
//   query = ufea @ W^T + b           (fused prologue, per-CTA)
//   S = leakyrelu2((query @ inter^T)/sqrt(D)); masked -> -9e15
//   online softmax over M; O = P @ inter; O /= rowsum
// BM=32 user rows per CTA, BN=64 item cols per tile, D=128. 128 threads.
// All smem float4 accesses xor-swizzled conflict-free.

#define D_  128
#define NU_ 10000
#define NI_ 12000
#define BM_ 32
#define BN_ 64
#define NT_ 128
#define NEG_BIG (-9e15f)

// smem (floats): ufea_s[32*128] q_s[32*128] i_s[64*128] p_s[32*64] + stats
#define OFF_UF   0
#define OFF_Q    4096
#define OFF_I    8192
#define OFF_P    16384
#define OFF_M    18432
#define OFF_L    (18432+32)
#define OFF_C    (18432+64)
#define SMEM_FLOATS (18432+96)

__global__ __launch_bounds__(NT_) void gat_fused_kernel(
    const float* __restrict__ ufea, const float* __restrict__ inter,
    const int*   __restrict__ adj,  const float* __restrict__ W,
    const float* __restrict__ bias, float* __restrict__ out)
{
    extern __shared__ float sm[];
    float* ufea_s = sm + OFF_UF;
    float* q_s    = sm + OFF_Q;
    float* i_s    = sm + OFF_I;
    float* p_s    = sm + OFF_P;
    float* row_m  = sm + OFF_M;
    float* row_l  = sm + OFF_L;
    float* row_c  = sm + OFF_C;

    const int tid = threadIdx.x;
    const int tx  = tid & 15,  ty  = tid >> 4;   // S-gemm layout: 16 x 8
    const int tx2 = tid & 31,  ty2 = tid >> 5;   // O-gemm layout: 32 x 4
    const int row0 = blockIdx.x * BM_;

    if (tid < BM_) { row_m[tid] = NEG_BIG; row_l[tid] = 0.f; }

    // ---- load ufea block [32 x 128], swizzled float4 slots ----
    #pragma unroll
    for (int it = 0; it < (BM_*D_/4)/NT_; ++it) {       // 8 iters
        int idx = it*NT_ + tid;
        int r = idx >> 5, k4 = idx & 31;
        int gr = min(row0 + r, NU_-1);
        float4 v = *(const float4*)(ufea + (size_t)gr*D_ + k4*4);
        *(float4*)(ufea_s + r*D_ + ((k4 ^ ((r>>2)&7))<<2)) = v;
    }

    // ---- prologue: q = ufea @ W^T + b  (two 64-col chunks, W staged in i_s) ----
    #pragma unroll 1
    for (int h = 0; h < 2; ++h) {
        __syncthreads();
        #pragma unroll
        for (int it = 0; it < (64*D_/4)/NT_; ++it) {    // 16 iters
            int idx = it*NT_ + tid;
            int r = idx >> 5, k4 = idx & 31;
            float4 v = *(const float4*)(W + (size_t)(h*64 + r)*D_ + k4*4);
            *(float4*)(i_s + r*D_ + ((k4 ^ ((r>>2)&7))<<2)) = v;
        }
        __syncthreads();
        float s[4][4] = {};
        #pragma unroll
        for (int k4 = 0; k4 < 32; ++k4) {
            float4 qv[4], wv[4];
            #pragma unroll
            for (int i = 0; i < 4; ++i)
                qv[i] = *(const float4*)(ufea_s + (ty*4+i)*D_ + ((k4 ^ (ty&7))<<2));
            #pragma unroll
            for (int j = 0; j < 4; ++j)
                wv[j] = *(const float4*)(i_s + (tx*4+j)*D_ + ((k4 ^ (tx&7))<<2));
            #pragma unroll
            for (int i = 0; i < 4; ++i)
                #pragma unroll
                for (int j = 0; j < 4; ++j) {
                    s[i][j] += qv[i].x*wv[j].x; s[i][j] += qv[i].y*wv[j].y;
                    s[i][j] += qv[i].z*wv[j].z; s[i][j] += qv[i].w*wv[j].w;
                }
        }
        float4 bv = *(const float4*)(bias + h*64 + tx*4);
        #pragma unroll
        for (int i = 0; i < 4; ++i) {
            int r = ty*4 + i;
            float4 o = make_float4(s[i][0]+bv.x, s[i][1]+bv.y, s[i][2]+bv.z, s[i][3]+bv.w);
            *(float4*)(q_s + r*D_ + (((h*16+tx) ^ ((r>>2)&7))<<2)) = o;
        }
    }

    float o_acc[8][4];
    #pragma unroll
    for (int i = 0; i < 8; ++i)
        #pragma unroll
        for (int j = 0; j < 4; ++j) o_acc[i][j] = 0.f;

    const int ntiles = (NI_ + BN_ - 1)/BN_;             // 188
    const float scale = 0.0883883476483184f;            // 1/sqrt(128)

    #pragma unroll 1
    for (int t = 0; t < ntiles; ++t) {
        const int col0 = t*BN_;

        // prefetch adj (int4 per row) straight from gmem
        int4 adjv[4];
        #pragma unroll
        for (int i = 0; i < 4; ++i) {
            int gr = min(row0 + ty*4 + i, NU_-1);
            int c  = col0 + tx*4;
            adjv[i] = (c < NI_) ? *(const int4*)(adj + (size_t)gr*NI_ + c)
                                : make_int4(0,0,0,0);
        }

        __syncthreads();                                // prev O-gemm done with i_s/p_s
        #pragma unroll
        for (int it = 0; it < (BN_*D_/4)/NT_; ++it) {   // 16 iters
            int idx = it*NT_ + tid;
            int r = idx >> 5, k4 = idx & 31;
            int gm = min(col0 + r, NI_-1);
            float4 v = *(const float4*)(inter + (size_t)gm*D_ + k4*4);
            *(float4*)(i_s + r*D_ + ((k4 ^ ((r>>2)&7))<<2)) = v;
        }
        __syncthreads();

        // ---- S = Q . I^T  (32x64), 4x4 per thread ----
        float s[4][4] = {};
        #pragma unroll
        for (int k4 = 0; k4 < 32; ++k4) {
            float4 qv[4], iv[4];
            #pragma unroll
            for (int i = 0; i < 4; ++i)
                qv[i] = *(const float4*)(q_s + (ty*4+i)*D_ + ((k4 ^ (ty&7))<<2));
            #pragma unroll
            for (int j = 0; j < 4; ++j)
                iv[j] = *(const float4*)(i_s + (tx*4+j)*D_ + ((k4 ^ (tx&7))<<2));
            #pragma unroll
            for (int i = 0; i < 4; ++i)
                #pragma unroll
                for (int j = 0; j < 4; ++j) {
                    s[i][j] += qv[i].x*iv[j].x; s[i][j] += qv[i].y*iv[j].y;
                    s[i][j] += qv[i].z*iv[j].z; s[i][j] += qv[i].w*iv[j].w;
                }
        }

        // ---- scale + leakyrelu(2) + mask + online softmax ----
        #pragma unroll
        for (int i = 0; i < 4; ++i) {
            int am[4] = {adjv[i].x, adjv[i].y, adjv[i].z, adjv[i].w};
            float mx = NEG_BIG;
            #pragma unroll
            for (int j = 0; j < 4; ++j) {
                float v = s[i][j] * scale;
                v = (v > 0.f) ? v : 2.f*v;
                v = (am[j] > 0) ? v : NEG_BIG;
                s[i][j] = v;
                mx = fmaxf(mx, v);
            }
            #pragma unroll
            for (int off = 8; off >= 1; off >>= 1)
                mx = fmaxf(mx, __shfl_xor_sync(0xffffffffu, mx, off));
            int r = ty*4 + i;
            float mprev = row_m[r];
            float mnew  = fmaxf(mprev, mx);
            float corr  = __expf(mprev - mnew);
            float psum  = 0.f;
            #pragma unroll
            for (int j = 0; j < 4; ++j) {
                float p = __expf(s[i][j] - mnew);
                s[i][j] = p;
                psum += p;
            }
            #pragma unroll
            for (int off = 8; off >= 1; off >>= 1)
                psum += __shfl_xor_sync(0xffffffffu, psum, off);
            if (tx == 0) {
                row_m[r] = mnew;
                row_l[r] = row_l[r]*corr + psum;
                row_c[r] = corr;
            }
            *(float4*)(p_s + r*BN_ + ((tx ^ (r&15))<<2)) =
                make_float4(s[i][0], s[i][1], s[i][2], s[i][3]);
        }
        __syncthreads();                                // p_s / row_c visible

        // ---- O = O*corr + P . I   (32x128), 8x4 per thread ----
        #pragma unroll
        for (int i = 0; i < 8; ++i) {
            float c = row_c[ty2*8 + i];
            #pragma unroll
            for (int j = 0; j < 4; ++j) o_acc[i][j] *= c;
        }
        #pragma unroll
        for (int m4 = 0; m4 < 16; ++m4) {
            float4 pv[8];
            #pragma unroll
            for (int i = 0; i < 8; ++i) {
                int r = ty2*8 + i;
                pv[i] = *(const float4*)(p_s + r*BN_ + ((m4 ^ (r&15))<<2));
            }
            #pragma unroll
            for (int mm = 0; mm < 4; ++mm) {
                int m = m4*4 + mm;
                float4 iv = *(const float4*)(i_s + m*D_ + ((tx2 ^ (m4&7))<<2));
                #pragma unroll
                for (int i = 0; i < 8; ++i) {
                    float p = (mm==0) ? pv[i].x : (mm==1) ? pv[i].y : (mm==2) ? pv[i].z : pv[i].w;
                    o_acc[i][0] += p*iv.x; o_acc[i][1] += p*iv.y;
                    o_acc[i][2] += p*iv.z; o_acc[i][3] += p*iv.w;
                }
            }
        }
    }

    // ---- epilogue: O / l ----
    __syncthreads();
    #pragma unroll
    for (int i = 0; i < 8; ++i) {
        int r = ty2*8 + i;
        int gr = row0 + r;
        if (gr < NU_) {
            float inv = __fdividef(1.f, row_l[r]);
            float4 o = make_float4(o_acc[i][0]*inv, o_acc[i][1]*inv,
                                   o_acc[i][2]*inv, o_acc[i][3]*inv);
            *(float4*)(out + (size_t)gr*D_ + tx2*4) = o;
        }
    }
}

extern "C" void kernel_launch(void* const* d_in, const int* in_sizes, int n_in,
                              void* d_out, int out_size)
{
    // positional defaults, then robust match by element counts (all distinct)
    const float* ufea  = (const float*)d_in[0];
    const float* inter = (const float*)d_in[1];
    const int*   adj   = (const int*)  d_in[2];
    const float* W     = (const float*)d_in[3];
    const float* bias  = (const float*)d_in[4];
    for (int i = 0; i < n_in; ++i) {
        int s = in_sizes[i];
        if      (s == NU_*D_)  ufea  = (const float*)d_in[i];
        else if (s == NI_*D_)  inter = (const float*)d_in[i];
        else if (s == NU_*NI_ || (long long)s == (long long)NU_*NI_) adj = (const int*)d_in[i];
        else if (s == D_*D_)   W     = (const float*)d_in[i];
        else if (s == D_)      bias  = (const float*)d_in[i];
    }

    static int smem_set = 0;
    (void)smem_set; // attribute set is idempotent; safe during graph capture (not a stream op)
    cudaFuncSetAttribute(gat_fused_kernel,
                         cudaFuncAttributeMaxDynamicSharedMemorySize,
                         SMEM_FLOATS * (int)sizeof(float));

    dim3 grid((NU_ + BM_ - 1)/BM_);   // 313 CTAs
    gat_fused_kernel<<<grid, NT_, SMEM_FLOATS * sizeof(float)>>>(
        ufea, inter, adj, W, bias, (float*)d_out);
}

// round 2
// speedup vs baseline: 1.0083x; 1.0083x over previous
#include <cuda_runtime.h>
#include <math.h>

// GAT forward_user, fully fused flash-style:
//   query = ufea @ W^T + b           (fused prologue, per-CTA)
//   S = leakyrelu2((query @ inter^T)/sqrt(D)); masked -> -9e15
//   online softmax over M; O = P @ inter; O /= rowsum
// BM=32 user rows per CTA, BN=64 item cols per tile, D=128. 128 threads.
// All smem float4 accesses xor-swizzled conflict-free.

#define D_  128
#define NU_ 10000
#define NI_ 12000
#define BM_ 32
#define BN_ 64
#define NT_ 128
#define NEG_BIG (-9e15f)

// smem (floats): ufea_s[32*128] q_s[32*128] i_s[64*128] p_s[32*64] + stats
#define OFF_UF   0
#define OFF_Q    4096
#define OFF_I    8192
#define OFF_P    16384
#define OFF_M    18432
#define OFF_L    (18432+32)
#define OFF_C    (18432+64)
#define SMEM_FLOATS (18432+96)

__global__ __launch_bounds__(NT_) void gat_fused_kernel(
    const float* __restrict__ ufea, const float* __restrict__ inter,
    const int*   __restrict__ adj,  const float* __restrict__ W,
    const float* __restrict__ bias, float* __restrict__ out)
{
    extern __shared__ float sm[];
    float* ufea_s = sm + OFF_UF;
    float* q_s    = sm + OFF_Q;
    float* i_s    = sm + OFF_I;
    float* p_s    = sm + OFF_P;
    float* row_m  = sm + OFF_M;
    float* row_l  = sm + OFF_L;
    float* row_c  = sm + OFF_C;

    const int tid = threadIdx.x;
    const int tx  = tid & 15,  ty  = tid >> 4;   // S-gemm layout: 16 x 8
    const int tx2 = tid & 31,  ty2 = tid >> 5;   // O-gemm layout: 32 x 4
    const int row0 = blockIdx.x * BM_;

    if (tid < BM_) { row_m[tid] = NEG_BIG; row_l[tid] = 0.f; }

    // ---- load ufea block [32 x 128], swizzled float4 slots ----
    #pragma unroll
    for (int it = 0; it < (BM_*D_/4)/NT_; ++it) {       // 8 iters
        int idx = it*NT_ + tid;
        int r = idx >> 5, k4 = idx & 31;
        int gr = min(row0 + r, NU_-1);
        float4 v = *(const float4*)(ufea + (size_t)gr*D_ + k4*4);
        *(float4*)(ufea_s + r*D_ + ((k4 ^ ((r>>2)&7))<<2)) = v;
    }

    // ---- prologue: q = ufea @ W^T + b  (two 64-col chunks, W staged in i_s) ----
    #pragma unroll 1
    for (int h = 0; h < 2; ++h) {
        __syncthreads();
        #pragma unroll
        for (int it = 0; it < (64*D_/4)/NT_; ++it) {    // 16 iters
            int idx = it*NT_ + tid;
            int r = idx >> 5, k4 = idx & 31;
            float4 v = *(const float4*)(W + (size_t)(h*64 + r)*D_ + k4*4);
            *(float4*)(i_s + r*D_ + ((k4 ^ ((r>>2)&7))<<2)) = v;
        }
        __syncthreads();
        float s[4][4] = {};
        #pragma unroll
        for (int k4 = 0; k4 < 32; ++k4) {
            float4 qv[4], wv[4];
            #pragma unroll
            for (int i = 0; i < 4; ++i)
                qv[i] = *(const float4*)(ufea_s + (ty*4+i)*D_ + ((k4 ^ (ty&7))<<2));
            #pragma unroll
            for (int j = 0; j < 4; ++j)
                wv[j] = *(const float4*)(i_s + (tx*4+j)*D_ + ((k4 ^ (tx&7))<<2));
            #pragma unroll
            for (int i = 0; i < 4; ++i)
                #pragma unroll
                for (int j = 0; j < 4; ++j) {
                    s[i][j] += qv[i].x*wv[j].x; s[i][j] += qv[i].y*wv[j].y;
                    s[i][j] += qv[i].z*wv[j].z; s[i][j] += qv[i].w*wv[j].w;
                }
        }
        float4 bv = *(const float4*)(bias + h*64 + tx*4);
        #pragma unroll
        for (int i = 0; i < 4; ++i) {
            int r = ty*4 + i;
            float4 o = make_float4(s[i][0]+bv.x, s[i][1]+bv.y, s[i][2]+bv.z, s[i][3]+bv.w);
            *(float4*)(q_s + r*D_ + (((h*16+tx) ^ ((r>>2)&7))<<2)) = o;
        }
    }

    float o_acc[8][4];
    #pragma unroll
    for (int i = 0; i < 8; ++i)
        #pragma unroll
        for (int j = 0; j < 4; ++j) o_acc[i][j] = 0.f;

    const int ntiles = (NI_ + BN_ - 1)/BN_;             // 188
    const float scale = 0.0883883476483184f;            // 1/sqrt(128)

    #pragma unroll 1
    for (int t = 0; t < ntiles; ++t) {
        const int col0 = t*BN_;

        // prefetch adj (int4 per row) straight from gmem
        int4 adjv[4];
        #pragma unroll
        for (int i = 0; i < 4; ++i) {
            int gr = min(row0 + ty*4 + i, NU_-1);
            int c  = col0 + tx*4;
            adjv[i] = (c < NI_) ? *(const int4*)(adj + (size_t)gr*NI_ + c)
                                : make_int4(0,0,0,0);
        }

        __syncthreads();                                // prev O-gemm done with i_s/p_s
        #pragma unroll
        for (int it = 0; it < (BN_*D_/4)/NT_; ++it) {   // 16 iters
            int idx = it*NT_ + tid;
            int r = idx >> 5, k4 = idx & 31;
            int gm = min(col0 + r, NI_-1);
            float4 v = *(const float4*)(inter + (size_t)gm*D_ + k4*4);
            *(float4*)(i_s + r*D_ + ((k4 ^ ((r>>2)&7))<<2)) = v;
        }
        __syncthreads();

        // ---- S = Q . I^T  (32x64), 4x4 per thread ----
        float s[4][4] = {};
        #pragma unroll
        for (int k4 = 0; k4 < 32; ++k4) {
            float4 qv[4], iv[4];
            #pragma unroll
            for (int i = 0; i < 4; ++i)
                qv[i] = *(const float4*)(q_s + (ty*4+i)*D_ + ((k4 ^ (ty&7))<<2));
            #pragma unroll
            for (int j = 0; j < 4; ++j)
                iv[j] = *(const float4*)(i_s + (tx*4+j)*D_ + ((k4 ^ (tx&7))<<2));
            #pragma unroll
            for (int i = 0; i < 4; ++i)
                #pragma unroll
                for (int j = 0; j < 4; ++j) {
                    s[i][j] += qv[i].x*iv[j].x; s[i][j] += qv[i].y*iv[j].y;
                    s[i][j] += qv[i].z*iv[j].z; s[i][j] += qv[i].w*iv[j].w;
                }
        }

        // ---- scale + leakyrelu(2) + mask + online softmax ----
        #pragma unroll
        for (int i = 0; i < 4; ++i) {
            int am[4] = {adjv[i].x, adjv[i].y, adjv[i].z, adjv[i].w};
            float mx = NEG_BIG;
            #pragma unroll
            for (int j = 0; j < 4; ++j) {
                float v = s[i][j] * scale;
                v = (v > 0.f) ? v : 2.f*v;
                v = (am[j] > 0) ? v : NEG_BIG;
                s[i][j] = v;
                mx = fmaxf(mx, v);
            }
            #pragma unroll
            for (int off = 8; off >= 1; off >>= 1)
                mx = fmaxf(mx, __shfl_xor_sync(0xffffffffu, mx, off));
            int r = ty*4 + i;
            float mprev = row_m[r];
            float mnew  = fmaxf(mprev, mx);
            float corr  = __expf(mprev - mnew);
            float psum  = 0.f;
            #pragma unroll
            for (int j = 0; j < 4; ++j) {
                float p = __expf(s[i][j] - mnew);
                s[i][j] = p;
                psum += p;
            }
            #pragma unroll
            for (int off = 8; off >= 1; off >>= 1)
                psum += __shfl_xor_sync(0xffffffffu, psum, off);
            if (tx == 0) {
                row_m[r] = mnew;
                row_l[r] = row_l[r]*corr + psum;
                row_c[r] = corr;
            }
            *(float4*)(p_s + r*BN_ + ((tx ^ (r&15))<<2)) =
                make_float4(s[i][0], s[i][1], s[i][2], s[i][3]);
        }
        __syncthreads();                                // p_s / row_c visible

        // ---- O = O*corr + P . I   (32x128), 8x4 per thread ----
        #pragma unroll
        for (int i = 0; i < 8; ++i) {
            float c = row_c[ty2*8 + i];
            #pragma unroll
            for (int j = 0; j < 4; ++j) o_acc[i][j] *= c;
        }
        #pragma unroll
        for (int m4 = 0; m4 < 16; ++m4) {
            float4 pv[8];
            #pragma unroll
            for (int i = 0; i < 8; ++i) {
                int r = ty2*8 + i;
                pv[i] = *(const float4*)(p_s + r*BN_ + ((m4 ^ (r&15))<<2));
            }
            #pragma unroll
            for (int mm = 0; mm < 4; ++mm) {
                int m = m4*4 + mm;
                float4 iv = *(const float4*)(i_s + m*D_ + ((tx2 ^ (m4&7))<<2));
                #pragma unroll
                for (int i = 0; i < 8; ++i) {
                    float p = (mm==0) ? pv[i].x : (mm==1) ? pv[i].y : (mm==2) ? pv[i].z : pv[i].w;
                    o_acc[i][0] += p*iv.x; o_acc[i][1] += p*iv.y;
                    o_acc[i][2] += p*iv.z; o_acc[i][3] += p*iv.w;
                }
            }
        }
    }

    // ---- epilogue: O / l ----
    __syncthreads();
    #pragma unroll
    for (int i = 0; i < 8; ++i) {
        int r = ty2*8 + i;
        int gr = row0 + r;
        if (gr < NU_) {
            float inv = __fdividef(1.f, row_l[r]);
            float4 o = make_float4(o_acc[i][0]*inv, o_acc[i][1]*inv,
                                   o_acc[i][2]*inv, o_acc[i][3]*inv);
            *(float4*)(out + (size_t)gr*D_ + tx2*4) = o;
        }
    }
}

extern "C" void kernel_launch(void* const* d_in, const int* in_sizes, int n_in,
                              void* d_out, int out_size)
{
    // positional defaults, then robust match by element counts (all distinct)
    const float* ufea  = (const float*)d_in[0];
    const float* inter = (const float*)d_in[1];
    const int*   adj   = (const int*)  d_in[2];
    const float* W     = (const float*)d_in[3];
    const float* bias  = (const float*)d_in[4];
    for (int i = 0; i < n_in; ++i) {
        int s = in_sizes[i];
        if      (s == NU_*D_)  ufea  = (const float*)d_in[i];
        else if (s == NI_*D_)  inter = (const float*)d_in[i];
        else if (s == NU_*NI_ || (long long)s == (long long)NU_*NI_) adj = (const int*)d_in[i];
        else if (s == D_*D_)   W     = (const float*)d_in[i];
        else if (s == D_)      bias  = (const float*)d_in[i];
    }

    static int smem_set = 0;
    (void)smem_set; // attribute set is idempotent; safe during graph capture (not a stream op)
    cudaFuncSetAttribute(gat_fused_kernel,
                         cudaFuncAttributeMaxDynamicSharedMemorySize,
                         SMEM_FLOATS * (int)sizeof(float));

    dim3 grid((NU_ + BM_ - 1)/BM_);   // 313 CTAs
    gat_fused_kernel<<<grid, NT_, SMEM_FLOATS * sizeof(float)>>>(
        ufea, inter, adj, W, bias, (float*)d_out);
}

// round 4
// speedup vs baseline: 2.1131x; 2.0958x over previous
#include <cuda_runtime.h>
#include <cstdint>
#include <math.h>

// GAT forward_user via warp-level mma.sync (tf32, m16n8k8) — portable sm_103 path.
//   Per CTA (64 user rows, item-split s of 2):
//     prologue: Q = ufea @ W^T + b in exact fp32, stored split Qb+Qs (tf32 pair)
//     loop over 94 item tiles (64 items):
//       S = Qb.I^T + Qs.I^T (2-pass tf32 => fp32-accurate scores)
//       P = exp(mask(leaky2(S/sqrt(D))));  l += rowsum(P)   [exp(-9e15)=0 => no max pass]
//       O += P.I (single-pass tf32, TMEM-free reg accumulators)
//   K2: out = (sum_s O_s)/(sum_s l_s)

#define D_     128
#define NU_    10000
#define NI_    12000
#define BM_    64
#define BN_    64
#define NRB_   157           // ceil(10000/64)
#define NRPAD_ (NRB_*BM_)    // 10048
#define NSPL_  2
#define IPS_   6000          // items per split
#define TILES_ 94            // ceil(6000/64)
#define NT_    256
#define SCALE_ 0.08838834764831843f

__device__ float g_op[NSPL_][(size_t)NRPAD_*D_];   // partial O (unnormalized)
__device__ float g_lp[NSPL_][NRPAD_];              // partial row sums

// ---- helpers ----
__device__ __forceinline__ uint32_t tf32u(float x){
    uint32_t u; asm("cvt.rna.tf32.f32 %0, %1;" : "=r"(u) : "f"(x)); return u;
}
__device__ __forceinline__ float tf32f(float x){ return __uint_as_float(tf32u(x)); }
__device__ __forceinline__ uint32_t fu(float x){ return __float_as_uint(x); }

__device__ __forceinline__ void mma8(float* d, const uint32_t* a, const uint32_t* b){
    asm volatile("mma.sync.aligned.m16n8k8.row.col.f32.tf32.tf32.f32 "
        "{%0,%1,%2,%3}, {%4,%5,%6,%7}, {%8,%9}, {%0,%1,%2,%3};"
        : "+f"(d[0]), "+f"(d[1]), "+f"(d[2]), "+f"(d[3])
        : "r"(a[0]), "r"(a[1]), "r"(a[2]), "r"(a[3]), "r"(b[0]), "r"(b[1]));
}

// xor-swizzled word index, row stride 128 / 64 floats (float4-safe)
__device__ __forceinline__ int swz128(int r, int c){
    return (r<<7) | ((((c>>2) ^ (r&7)) << 2) | (c&3));
}
__device__ __forceinline__ int swz64(int r, int c){
    return (r<<6) | ((((c>>2) ^ (r&7)) << 2) | (c&3));
}

// smem float offsets
#define O_QB 0
#define O_QS 8192
#define O_I  16384
#define O_P  24576
#define O_L  28672
#define SMEM_F (28672+128)   // 115200 bytes

__global__ __launch_bounds__(NT_, 2)
void gat_main(const float* __restrict__ ufea, const float* __restrict__ inter,
              const int* __restrict__ adj, const float* __restrict__ W,
              const float* __restrict__ bias)
{
    extern __shared__ float sm[];
    float* sQb = sm + O_QB;
    float* sQs = sm + O_QS;
    float* sI  = sm + O_I;
    float* sP  = sm + O_P;
    float* sL  = sm + O_L;

    const int tid  = threadIdx.x;
    const int lane = tid & 31, warp = tid >> 5;
    const int g    = lane >> 2, tig = lane & 3;
    const int wm   = warp >> 1, wn  = warp & 1;
    const int row0  = blockIdx.x * BM_;
    const int split = blockIdx.y;
    const int item0 = split * IPS_;

    // ================= prologue: Q = ufea @ W^T + b (fp32 exact) ==========
    // stage ufea [64x128] into sI
    #pragma unroll
    for (int it = 0; it < 8; ++it){
        int idx = it*NT_ + tid;
        int r = idx >> 5, c4 = idx & 31;
        int gr = min(row0 + r, NU_-1);
        float4 v = *(const float4*)(ufea + (size_t)gr*D_ + c4*4);
        *(float4*)(sI + swz128(r, c4*4)) = v;
    }
    const int tx = tid & 15, ty = tid >> 4;    // 16x16 thread grid
    #pragma unroll 1
    for (int h = 0; h < 4; ++h){
        __syncthreads();
        // stage W rows [h*32, h*32+32) into sP
        #pragma unroll
        for (int it = 0; it < 4; ++it){
            int idx = it*NT_ + tid;
            int lr = idx >> 5, c4 = idx & 31;
            float4 w = *(const float4*)(W + (size_t)(h*32+lr)*D_ + c4*4);
            *(float4*)(sP + swz128(lr, c4*4)) = w;
        }
        __syncthreads();
        float acc[4][2] = {};
        #pragma unroll
        for (int k4 = 0; k4 < 32; ++k4){
            float4 wv[2];
            #pragma unroll
            for (int j = 0; j < 2; ++j)
                wv[j] = *(const float4*)(sP + swz128(tx*2+j, k4*4));
            #pragma unroll
            for (int i = 0; i < 4; ++i){
                float4 uv = *(const float4*)(sI + swz128(ty*4+i, k4*4));
                #pragma unroll
                for (int j = 0; j < 2; ++j){
                    acc[i][j] += uv.x*wv[j].x; acc[i][j] += uv.y*wv[j].y;
                    acc[i][j] += uv.z*wv[j].z; acc[i][j] += uv.w*wv[j].w;
                }
            }
        }
        #pragma unroll
        for (int i = 0; i < 4; ++i)
            #pragma unroll
            for (int j = 0; j < 2; ++j){
                int r = ty*4 + i, c = h*32 + tx*2 + j;
                float q = acc[i][j] + bias[c];
                uint32_t qb = tf32u(q);
                float qbf = __uint_as_float(qb);
                sQb[swz128(r,c)] = qbf;
                sQs[swz128(r,c)] = tf32f(q - qbf);
            }
    }

    // ================= mainloop =================
    float oacc[8][4];
    #pragma unroll
    for (int i = 0; i < 8; ++i)
        #pragma unroll
        for (int j = 0; j < 4; ++j) oacc[i][j] = 0.f;
    float lacc0 = 0.f, lacc1 = 0.f;

    const int m0 = wm*16, n0 = wn*32, nd0 = wn*64;
    const int gr0 = min(row0 + m0 + g,     NU_-1);
    const int gr1 = min(row0 + m0 + 8 + g, NU_-1);
    const size_t arow0 = (size_t)gr0*NI_ + item0;
    const size_t arow1 = (size_t)gr1*NI_ + item0;

    #pragma unroll 1
    for (int t = 0; t < TILES_; ++t){
        __syncthreads();                         // prev O-gemm done with sI/sP
        // load I tile [64 items x 128 dims], tf32-rounded
        #pragma unroll
        for (int it = 0; it < 8; ++it){
            int idx = it*NT_ + tid;
            int r = idx >> 5, c4 = idx & 31;
            int gm = min(item0 + t*BN_ + r, NI_-1);
            float4 v = *(const float4*)(inter + (size_t)gm*D_ + c4*4);
            v.x = tf32f(v.x); v.y = tf32f(v.y); v.z = tf32f(v.z); v.w = tf32f(v.w);
            *(float4*)(sI + swz128(r, c4*4)) = v;
        }
        __syncthreads();

        // ---- S = Qb.I^T + Qs.I^T  (warp: 16 rows x 32 cols) ----
        float sacc[4][4];
        #pragma unroll
        for (int nf = 0; nf < 4; ++nf)
            #pragma unroll
            for (int j = 0; j < 4; ++j) sacc[nf][j] = 0.f;
        #pragma unroll 4
        for (int ks = 0; ks < 16; ++ks){
            const int ca = ks*8 + tig, cb = ks*8 + 4 + tig;
            uint32_t ab[4], as2[4];
            ab[0]  = fu(sQb[swz128(m0+g,   ca)]);
            ab[1]  = fu(sQb[swz128(m0+8+g, ca)]);
            ab[2]  = fu(sQb[swz128(m0+g,   cb)]);
            ab[3]  = fu(sQb[swz128(m0+8+g, cb)]);
            as2[0] = fu(sQs[swz128(m0+g,   ca)]);
            as2[1] = fu(sQs[swz128(m0+8+g, ca)]);
            as2[2] = fu(sQs[swz128(m0+g,   cb)]);
            as2[3] = fu(sQs[swz128(m0+8+g, cb)]);
            #pragma unroll
            for (int nf = 0; nf < 4; ++nf){
                const int nn = n0 + nf*8 + g;
                uint32_t b[2] = { fu(sI[swz128(nn, ca)]), fu(sI[swz128(nn, cb)]) };
                mma8(sacc[nf], ab, b);
                mma8(sacc[nf], as2, b);
            }
        }

        // ---- epilogue: scale, leaky2, mask, exp; write P (tf32) ----
        #pragma unroll
        for (int nf = 0; nf < 4; ++nf){
            const int c0 = n0 + nf*8 + 2*tig;
            const int lc = t*BN_ + c0;
            int2 a0 = make_int2(0,0), a1 = make_int2(0,0);
            if (lc < IPS_){
                a0 = *(const int2*)(adj + arow0 + lc);
                a1 = *(const int2*)(adj + arow1 + lc);
            }
            float v00 = sacc[nf][0]*SCALE_; v00 = fminf(v00, 2.f*v00);
            float v01 = sacc[nf][1]*SCALE_; v01 = fminf(v01, 2.f*v01);
            float v10 = sacc[nf][2]*SCALE_; v10 = fminf(v10, 2.f*v10);
            float v11 = sacc[nf][3]*SCALE_; v11 = fminf(v11, 2.f*v11);
            float p00 = (a0.x > 0) ? __expf(v00) : 0.f;
            float p01 = (a0.y > 0) ? __expf(v01) : 0.f;
            float p10 = (a1.x > 0) ? __expf(v10) : 0.f;
            float p11 = (a1.y > 0) ? __expf(v11) : 0.f;
            lacc0 += p00 + p01;
            lacc1 += p10 + p11;
            *(float2*)(sP + swz64(m0+g,   c0)) = make_float2(tf32f(p00), tf32f(p01));
            *(float2*)(sP + swz64(m0+8+g, c0)) = make_float2(tf32f(p10), tf32f(p11));
        }
        __syncthreads();                         // P visible

        // ---- O += P.I  (warp: 16 rows x 64 dims) ----
        #pragma unroll 4
        for (int ks = 0; ks < 8; ++ks){
            const int ca = ks*8 + tig, cb = ks*8 + 4 + tig;
            uint32_t pa[4];
            pa[0] = fu(sP[swz64(m0+g,   ca)]);
            pa[1] = fu(sP[swz64(m0+8+g, ca)]);
            pa[2] = fu(sP[swz64(m0+g,   cb)]);
            pa[3] = fu(sP[swz64(m0+8+g, cb)]);
            #pragma unroll
            for (int nf = 0; nf < 8; ++nf){
                const int dd = nd0 + nf*8 + g;
                uint32_t b[2] = { fu(sI[swz128(ca, dd)]), fu(sI[swz128(cb, dd)]) };
                mma8(oacc[nf], pa, b);
            }
        }
    }

    // ---- l reduction: sum over tig quad, then over the 2 n-warps ----
    lacc0 += __shfl_xor_sync(0xffffffffu, lacc0, 1);
    lacc0 += __shfl_xor_sync(0xffffffffu, lacc0, 2);
    lacc1 += __shfl_xor_sync(0xffffffffu, lacc1, 1);
    lacc1 += __shfl_xor_sync(0xffffffffu, lacc1, 2);
    if (tig == 0){
        sL[wn*64 + m0 + g]     = lacc0;
        sL[wn*64 + m0 + 8 + g] = lacc1;
    }
    __syncthreads();
    if (tid < BM_) g_lp[split][row0 + tid] = sL[tid] + sL[64 + tid];

    // ---- write unnormalized partial O ----
    {
        const int r0g = row0 + m0 + g, r1g = row0 + m0 + 8 + g;
        #pragma unroll
        for (int nf = 0; nf < 8; ++nf){
            const int dd = nd0 + nf*8 + 2*tig;
            if (r0g < NU_)
                *(float2*)(&g_op[split][(size_t)r0g*D_ + dd]) =
                    make_float2(oacc[nf][0], oacc[nf][1]);
            if (r1g < NU_)
                *(float2*)(&g_op[split][(size_t)r1g*D_ + dd]) =
                    make_float2(oacc[nf][2], oacc[nf][3]);
        }
    }
}

// ================= combine splits & normalize =================
__global__ __launch_bounds__(256) void gat_reduce(float* __restrict__ out)
{
    int idx = blockIdx.x*256 + threadIdx.x;      // over NU_*32 float4s
    int rr = idx >> 5, c4 = idx & 31;
    if (rr >= NU_) return;
    float l = g_lp[0][rr] + g_lp[1][rr];
    float4 a = *(const float4*)(&g_op[0][(size_t)rr*D_ + c4*4]);
    float4 b = *(const float4*)(&g_op[1][(size_t)rr*D_ + c4*4]);
    float inv = 1.0f / l;
    float4 o = make_float4((a.x+b.x)*inv, (a.y+b.y)*inv,
                           (a.z+b.z)*inv, (a.w+b.w)*inv);
    *(float4*)(out + (size_t)rr*D_ + c4*4) = o;
}

extern "C" void kernel_launch(void* const* d_in, const int* in_sizes, int n_in,
                              void* d_out, int out_size)
{
    const float* ufea  = (const float*)d_in[0];
    const float* inter = (const float*)d_in[1];
    const int*   adj   = (const int*)  d_in[2];
    const float* W     = (const float*)d_in[3];
    const float* bias  = (const float*)d_in[4];
    for (int i = 0; i < n_in; ++i) {
        int s = in_sizes[i];
        if      (s == NU_*D_)  ufea  = (const float*)d_in[i];
        else if (s == NI_*D_)  inter = (const float*)d_in[i];
        else if (s == NU_*NI_) adj   = (const int*)d_in[i];
        else if (s == D_*D_)   W     = (const float*)d_in[i];
        else if (s == D_)      bias  = (const float*)d_in[i];
    }

    cudaFuncSetAttribute(gat_main, cudaFuncAttributeMaxDynamicSharedMemorySize,
                         SMEM_F * (int)sizeof(float));

    dim3 grid(NRB_, NSPL_);                       // 157 x 2 = 314 CTAs
    gat_main<<<grid, NT_, SMEM_F * sizeof(float)>>>(ufea, inter, adj, W, bias);
    gat_reduce<<<(NU_*32 + 255)/256, 256>>>((float*)d_out);
}

// round 5
// speedup vs baseline: 3.3198x; 1.5710x over previous
#include <cuda_runtime.h>
#include <cstdint>

// GAT forward_user, mma.sync tf32 single-pass, fragment-packed smem operands.
//   Per CTA (64 user rows, item-split s of 2):
//     prologue: Q = ufea@W^T+b exact fp32 -> tf32, stored in A-fragment layout
//     per 64-item tile: cp.async adj; I -> B-fragment layout (tf32);
//       S = Q.I^T; P = exp(mask(leaky2(S/sqrt(D)))); l += rowsum;
//       O += P.I  (O's B operand re-indexed out of the same packed I buffer)
//   reduce kernel: out = (sum_s O_s)/(sum_s l_s)

#define D_     128
#define NU_    10000
#define NI_    12000
#define BM_    64
#define NRB_   157
#define NRPAD_ (NRB_*BM_)
#define NSPL_  2
#define IPS_   6000
#define TILES_ 94
#define NT_    256
#define SCALE_ 0.08838834764831843f

__device__ float g_op[NSPL_][(size_t)NRPAD_*D_];
__device__ float g_lp[NSPL_][NRPAD_];

// ---- helpers ----
__device__ __forceinline__ uint32_t tf32u(float x){
    uint32_t u; asm("cvt.rna.tf32.f32 %0, %1;" : "=r"(u) : "f"(x)); return u;
}
__device__ __forceinline__ float tf32f(float x){ return __uint_as_float(tf32u(x)); }
__device__ __forceinline__ uint32_t fu(float x){ return __float_as_uint(x); }

__device__ __forceinline__ void mma8(float* d, const uint32_t* a, const uint32_t* b){
    asm volatile("mma.sync.aligned.m16n8k8.row.col.f32.tf32.tf32.f32 "
        "{%0,%1,%2,%3}, {%4,%5,%6,%7}, {%8,%9}, {%0,%1,%2,%3};"
        : "+f"(d[0]), "+f"(d[1]), "+f"(d[2]), "+f"(d[3])
        : "r"(a[0]), "r"(a[1]), "r"(a[2]), "r"(a[3]), "r"(b[0]), "r"(b[1]));
}
__device__ __forceinline__ uint32_t smem_u32(const void* p){
    uint32_t a;
    asm("{ .reg .u64 t; cvta.to.shared.u64 t, %1; cvt.u32.u64 %0, t; }" : "=r"(a) : "l"(p));
    return a;
}
__device__ __forceinline__ void cpa8(uint32_t dst, const void* src){
    asm volatile("cp.async.ca.shared.global [%0], [%1], 8;" :: "r"(dst), "l"(src));
}
#define CP_COMMIT() asm volatile("cp.async.commit_group;" ::: "memory")
#define CP_WAIT0()  asm volatile("cp.async.wait_group 0;" ::: "memory")

__device__ __forceinline__ int swz128(int r, int c){
    return (r<<7) | ((((c>>2) ^ (r&7)) << 2) | (c&3));
}
__device__ __forceinline__ int swz64(int r, int c){
    return (r<<6) | ((((c>>2) ^ (r&7)) << 2) | (c&3));
}
// bank swizzle for the I fragment buffer (per 32-word lane slot)
__device__ __forceinline__ int swzS(int L){ return ((L ^ (L>>4)) & 15) * 2; }

// smem float offsets
#define O_QF  0        // Q A-fragments: [wm4][ks16][lane32][4]  = 8192 f
#define O_IF  8192     // I B-fragments: [wnf8][lane32][32]      = 8192 f
#define O_P   16384    // P [64][64] swz64                       = 4096 f
#define O_ADJ 20480    // adj ints [64][66]                      = 4224 i
#define O_L   24704    // 128 f
#define SMEM_F 24832   // 99328 bytes

__global__ __launch_bounds__(NT_, 2)
void gat_main(const float* __restrict__ ufea, const float* __restrict__ inter,
              const int* __restrict__ adj, const float* __restrict__ W,
              const float* __restrict__ bias)
{
    extern __shared__ float sm[];
    float* sQF = sm + O_QF;
    float* sIF = sm + O_IF;
    float* sP  = sm + O_P;
    int*   sA  = (int*)(sm + O_ADJ);
    float* sL  = sm + O_L;
    const uint32_t sA_b = smem_u32(sA);

    const int tid  = threadIdx.x;
    const int lane = tid & 31, warp = tid >> 5;
    const int g    = lane >> 2, tig = lane & 3;
    const int wm   = warp >> 1, wn  = warp & 1;
    const int row0  = blockIdx.x * BM_;
    const int split = blockIdx.y;
    const int item0 = split * IPS_;

    // ============ prologue: Q = ufea @ W^T + b (fp32 exact) -> Qfrag ========
    #pragma unroll
    for (int it = 0; it < 8; ++it){
        int idx = it*NT_ + tid;
        int r = idx >> 5, c4 = idx & 31;
        int gr = min(row0 + r, NU_-1);
        float4 v = *(const float4*)(ufea + (size_t)gr*D_ + c4*4);
        *(float4*)(sIF + swz128(r, c4*4)) = v;      // stage ufea in sIF
    }
    const int tx = tid & 15, ty = tid >> 4;
    #pragma unroll 1
    for (int h = 0; h < 4; ++h){
        __syncthreads();
        #pragma unroll
        for (int it = 0; it < 4; ++it){             // stage W rows [h*32,+32) in sP
            int idx = it*NT_ + tid;
            int lr = idx >> 5, c4 = idx & 31;
            float4 w = *(const float4*)(W + (size_t)(h*32+lr)*D_ + c4*4);
            *(float4*)(sP + swz128(lr, c4*4)) = w;
        }
        __syncthreads();
        float acc[4][2] = {};
        #pragma unroll
        for (int k4 = 0; k4 < 32; ++k4){
            float4 wv[2];
            #pragma unroll
            for (int j = 0; j < 2; ++j)
                wv[j] = *(const float4*)(sP + swz128(tx*2+j, k4*4));
            #pragma unroll
            for (int i = 0; i < 4; ++i){
                float4 uv = *(const float4*)(sIF + swz128(ty*4+i, k4*4));
                #pragma unroll
                for (int j = 0; j < 2; ++j){
                    acc[i][j] += uv.x*wv[j].x; acc[i][j] += uv.y*wv[j].y;
                    acc[i][j] += uv.z*wv[j].z; acc[i][j] += uv.w*wv[j].w;
                }
            }
        }
        #pragma unroll
        for (int i = 0; i < 4; ++i)
            #pragma unroll
            for (int j = 0; j < 2; ++j){
                int r = ty*4 + i, c = h*32 + tx*2 + j;
                float q = acc[i][j] + bias[c];
                int wmq = r>>4, rr = r&15;
                int ks = c>>3, tg = c&3, kh = (c>>2)&1;
                sQF[((wmq*16 + ks)*32 + (rr&7)*4 + tg)*4 + kh*2 + (rr>>3)]
                    = tf32f(q);
            }
    }

    // ============ mainloop ============
    float oacc[8][4];
    #pragma unroll
    for (int i = 0; i < 8; ++i)
        #pragma unroll
        for (int j = 0; j < 4; ++j) oacc[i][j] = 0.f;
    float lacc0 = 0.f, lacc1 = 0.f;

    const int m0 = wm*16, n0 = wn*32, nd0 = wn*64;
    const int w8 = warp;                         // 0..7: loader row group
    const int cc2 = (tid & 31) * 2;              // adj copy column (ints)
    const int swzl = swzS(lane);                 // S B-frag reader swizzle
    const int laneS = tig*4 + (g&3);             // O B-frag source lane
    const int ls2  = laneS*2;
    const int khd  = (g>>2)&1;
    const int szw[4] = { swzS(w8*4+0), swzS(w8*4+1), swzS(w8*4+2), swzS(w8*4+3) };

    #pragma unroll 1
    for (int t = 0; t < TILES_; ++t){
        // ---- cp.async adj tile [64 x 64] -> sA[64][66] (latency hidden) ----
        {
            const int tcol = t*64;
            #pragma unroll
            for (int itc = 0; itc < 8; ++itc){
                int rowa = itc*8 + w8;
                int gr = min(row0 + rowa, NU_-1);
                int lcc = tcol + cc2;
                const int* src = adj + (size_t)gr*NI_ + item0
                               + ((lcc < IPS_) ? lcc : 0);
                cpa8(sA_b + (uint32_t)((rowa*66 + cc2)*4), src);
            }
            CP_COMMIT();
        }
        __syncthreads();                         // O-mma(t-1) done with sIF/sP

        // ---- load I tile -> B-fragment layout (tf32) ----
        #pragma unroll
        for (int it_ = 0; it_ < 8; ++it_){
            int item = it_*8 + w8;
            int gm = min(item0 + t*64 + item, NI_-1);
            float4 v = *(const float4*)(inter + (size_t)gm*D_ + lane*4);
            int base = it_*1024 + w8*128;
            int lo = (lane & 30), hi = (lane & 1);
            sIF[base +   0 + ((lo ^ szw[0]) | hi)] = tf32f(v.x);
            sIF[base +  32 + ((lo ^ szw[1]) | hi)] = tf32f(v.y);
            sIF[base +  64 + ((lo ^ szw[2]) | hi)] = tf32f(v.z);
            sIF[base +  96 + ((lo ^ szw[3]) | hi)] = tf32f(v.w);
        }
        CP_WAIT0();
        __syncthreads();

        // ---- S = Q . I^T  (warp: 16 rows x 32 items) ----
        float sacc[4][4];
        #pragma unroll
        for (int nf = 0; nf < 4; ++nf)
            #pragma unroll
            for (int j = 0; j < 4; ++j) sacc[nf][j] = 0.f;
        #pragma unroll 8
        for (int ks = 0; ks < 16; ++ks){
            uint4 a4 = *(const uint4*)(sQF + ((wm*16 + ks)*32 + lane)*4);
            const uint32_t A[4] = { a4.x, a4.y, a4.z, a4.w };
            #pragma unroll
            for (int nf = 0; nf < 4; ++nf){
                uint2 b2 = *(const uint2*)(sIF + ((wn*4 + nf)*32 + lane)*32
                                               + ((ks*2) ^ swzl));
                const uint32_t B[2] = { b2.x, b2.y };
                mma8(sacc[nf], A, B);
            }
        }

        // ---- epilogue: scale, leaky2, mask(adj from smem), exp; P -> sP ----
        #pragma unroll
        for (int nf = 0; nf < 4; ++nf){
            const int c0 = n0 + nf*8 + 2*tig;
            const int lc = t*64 + c0;
            int2 a0 = make_int2(0,0), a1 = make_int2(0,0);
            if (lc < IPS_){
                a0 = *(const int2*)(sA + (m0+g)*66 + c0);
                a1 = *(const int2*)(sA + (m0+8+g)*66 + c0);
            }
            float v00 = sacc[nf][0]*SCALE_; v00 = fminf(v00, 2.f*v00);
            float v01 = sacc[nf][1]*SCALE_; v01 = fminf(v01, 2.f*v01);
            float v10 = sacc[nf][2]*SCALE_; v10 = fminf(v10, 2.f*v10);
            float v11 = sacc[nf][3]*SCALE_; v11 = fminf(v11, 2.f*v11);
            float p00 = (a0.x > 0) ? __expf(v00) : 0.f;
            float p01 = (a0.y > 0) ? __expf(v01) : 0.f;
            float p10 = (a1.x > 0) ? __expf(v10) : 0.f;
            float p11 = (a1.y > 0) ? __expf(v11) : 0.f;
            lacc0 += p00 + p01;
            lacc1 += p10 + p11;
            *(float2*)(sP + swz64(m0+g,   c0)) = make_float2(tf32f(p00), tf32f(p01));
            *(float2*)(sP + swz64(m0+8+g, c0)) = make_float2(tf32f(p10), tf32f(p11));
        }
        __syncthreads();                         // P visible, adj consumed

        // ---- O += P . I  (warp: 16 rows x 64 dims) ----
        #pragma unroll 4
        for (int ks_o = 0; ks_o < 8; ++ks_o){
            const int ca = ks_o*8 + tig, cb = ca + 4;
            uint32_t pa[4];
            pa[0] = fu(sP[swz64(m0+g,   ca)]);
            pa[1] = fu(sP[swz64(m0+8+g, ca)]);
            pa[2] = fu(sP[swz64(m0+g,   cb)]);
            pa[3] = fu(sP[swz64(m0+8+g, cb)]);
            #pragma unroll
            for (int nf = 0; nf < 8; ++nf){
                const int ksd2 = (wn*8 + nf)*2;
                uint32_t B[2];
                B[0] = fu(sIF[(ks_o*32 + laneS)*32      + ((ksd2 ^ ls2)     | khd)]);
                B[1] = fu(sIF[(ks_o*32 + laneS + 16)*32 + ((ksd2 ^ ls2 ^ 2) | khd)]);
                mma8(oacc[nf], pa, B);
            }
        }
    }

    // ---- l reduction ----
    lacc0 += __shfl_xor_sync(0xffffffffu, lacc0, 1);
    lacc0 += __shfl_xor_sync(0xffffffffu, lacc0, 2);
    lacc1 += __shfl_xor_sync(0xffffffffu, lacc1, 1);
    lacc1 += __shfl_xor_sync(0xffffffffu, lacc1, 2);
    if (tig == 0){
        sL[wn*64 + m0 + g]     = lacc0;
        sL[wn*64 + m0 + 8 + g] = lacc1;
    }
    __syncthreads();
    if (tid < BM_) g_lp[split][row0 + tid] = sL[tid] + sL[64 + tid];

    // ---- write unnormalized partial O ----
    {
        const int r0g = row0 + m0 + g, r1g = row0 + m0 + 8 + g;
        #pragma unroll
        for (int nf = 0; nf < 8; ++nf){
            const int dd = nd0 + nf*8 + 2*tig;
            if (r0g < NU_)
                *(float2*)(&g_op[split][(size_t)r0g*D_ + dd]) =
                    make_float2(oacc[nf][0], oacc[nf][1]);
            if (r1g < NU_)
                *(float2*)(&g_op[split][(size_t)r1g*D_ + dd]) =
                    make_float2(oacc[nf][2], oacc[nf][3]);
        }
    }
}

// ================= combine splits & normalize =================
__global__ __launch_bounds__(256) void gat_reduce(float* __restrict__ out)
{
    int idx = blockIdx.x*256 + threadIdx.x;
    int rr = idx >> 5, c4 = idx & 31;
    if (rr >= NU_) return;
    float l = g_lp[0][rr] + g_lp[1][rr];
    float4 a = *(const float4*)(&g_op[0][(size_t)rr*D_ + c4*4]);
    float4 b = *(const float4*)(&g_op[1][(size_t)rr*D_ + c4*4]);
    float inv = 1.0f / l;
    float4 o = make_float4((a.x+b.x)*inv, (a.y+b.y)*inv,
                           (a.z+b.z)*inv, (a.w+b.w)*inv);
    *(float4*)(out + (size_t)rr*D_ + c4*4) = o;
}

extern "C" void kernel_launch(void* const* d_in, const int* in_sizes, int n_in,
                              void* d_out, int out_size)
{
    const float* ufea  = (const float*)d_in[0];
    const float* inter = (const float*)d_in[1];
    const int*   adj   = (const int*)  d_in[2];
    const float* W     = (const float*)d_in[3];
    const float* bias  = (const float*)d_in[4];
    for (int i = 0; i < n_in; ++i) {
        int s = in_sizes[i];
        if      (s == NU_*D_)  ufea  = (const float*)d_in[i];
        else if (s == NI_*D_)  inter = (const float*)d_in[i];
        else if (s == NU_*NI_) adj   = (const int*)d_in[i];
        else if (s == D_*D_)   W     = (const float*)d_in[i];
        else if (s == D_)      bias  = (const float*)d_in[i];
    }

    cudaFuncSetAttribute(gat_main, cudaFuncAttributeMaxDynamicSharedMemorySize,
                         SMEM_F * (int)sizeof(float));

    dim3 grid(NRB_, NSPL_);                       // 157 x 2 = 314 CTAs
    gat_main<<<grid, NT_, SMEM_F * sizeof(float)>>>(ufea, inter, adj, W, bias);
    gat_reduce<<<(NU_*32 + 255)/256, 256>>>((float*)d_out);
}

// round 6
// speedup vs baseline: 4.6413x; 1.3981x over previous
#include <cuda_runtime.h>
#include <cuda_fp16.h>
#include <cstdint>

// GAT forward_user via mma.sync m16n8k16 fp16 (portable sm_103 HMMA path).
//   Per CTA (64 user rows, item-split s of 2):
//     prologue: Q = ufea@W^T+b exact fp32 -> fp16 A-fragments in smem
//     per 64-item tile: cp.async adj; I -> fp16 B-fragments (two layouts:
//       S-layout pairs dims, O-layout pairs items);
//       S = Q.I^T (fp32 acc); P = exp(mask(leaky2(S/sqrt(D)))); l += rowsum;
//       P -> fp16 A-fragments (direct from accumulator regs); O += P.I
//   reduce kernel: out = (sum_s O_s)/(sum_s l_s)

#define D_     128
#define NU_    10000
#define NI_    12000
#define BM_    64
#define NRB_   157
#define NRPAD_ (NRB_*BM_)
#define NSPL_  2
#define IPS_   6000
#define TILES_ 94
#define NT_    256
#define SCALE_ 0.08838834764831843f

__device__ float g_op[NSPL_][(size_t)NRPAD_*D_];
__device__ float g_lp[NSPL_][NRPAD_];

// ---- helpers ----
__device__ __forceinline__ uint32_t h2u(float a, float b){
    __half2 h = __floats2half2_rn(a, b);
    return *(uint32_t*)&h;
}
__device__ __forceinline__ void mma16(float* d, const uint32_t* a, const uint32_t* b){
    asm volatile("mma.sync.aligned.m16n8k16.row.col.f32.f16.f16.f32 "
        "{%0,%1,%2,%3}, {%4,%5,%6,%7}, {%8,%9}, {%0,%1,%2,%3};"
        : "+f"(d[0]), "+f"(d[1]), "+f"(d[2]), "+f"(d[3])
        : "r"(a[0]), "r"(a[1]), "r"(a[2]), "r"(a[3]), "r"(b[0]), "r"(b[1]));
}
__device__ __forceinline__ uint32_t smem_u32(const void* p){
    uint32_t a;
    asm("{ .reg .u64 t; cvta.to.shared.u64 t, %1; cvt.u32.u64 %0, t; }" : "=r"(a) : "l"(p));
    return a;
}
__device__ __forceinline__ void cpa8(uint32_t dst, const void* src){
    asm volatile("cp.async.ca.shared.global [%0], [%1], 8;" :: "r"(dst), "l"(src));
}
#define CP_COMMIT() asm volatile("cp.async.commit_group;" ::: "memory")
#define CP_WAIT0()  asm volatile("cp.async.wait_group 0;" ::: "memory")

__device__ __forceinline__ int swz128(int r, int c){
    return (r<<7) | ((((c>>2) ^ (r&7)) << 2) | (c&3));
}

// smem byte offsets
#define B_SQ   0        // Q A-frag:  [wm*8+ks:32][lane32][uint4]      16384
#define B_SBS  16384    // I B-frag S:[jg8][ks8][lane32][uint2]        16384
#define B_SBO  32768    // I B-frag O:[ng16][ks4][lane32][uint2]       16384
#define B_SP   49152    // P A-frag:  [wm*4+kso:16][lane32][uint4]      8192
#define B_ADJ  57344    // adj ints [64][66]                           16896
#define B_L    74240    // 128 floats                                    512
#define SMEM_B 74752

__global__ __launch_bounds__(NT_, 2)
void gat_main(const float* __restrict__ ufea, const float* __restrict__ inter,
              const int* __restrict__ adj, const float* __restrict__ W,
              const float* __restrict__ bias)
{
    extern __shared__ char smc[];
    uint4*    sQ  = (uint4*)(smc + B_SQ);
    uint32_t* sBS = (uint32_t*)(smc + B_SBS);
    uint32_t* sBO = (uint32_t*)(smc + B_SBO);
    uint4*    sP  = (uint4*)(smc + B_SP);
    int*      sA  = (int*)(smc + B_ADJ);
    float*    sL  = (float*)(smc + B_L);
    const uint32_t sA_b = smem_u32(sA);

    const int tid  = threadIdx.x;
    const int lane = tid & 31, warp = tid >> 5;
    const int g    = lane >> 2, tig = lane & 3;
    const int wm   = warp >> 1, wn  = warp & 1;
    const int row0  = blockIdx.x * BM_;
    const int split = blockIdx.y;
    const int item0 = split * IPS_;

    // ====== prologue: Q = ufea @ W^T + b (fp32 exact) -> fp16 A-frags ======
    {
        float* pU = (float*)(smc + B_SBS);     // 32KB staging (SBS+SBO)
        float* pW = (float*)(smc + B_SP);      // 16KB staging (SP+ADJ head)
        #pragma unroll
        for (int it = 0; it < 8; ++it){
            int idx = it*NT_ + tid;
            int r = idx >> 5, c4 = idx & 31;
            int gr = min(row0 + r, NU_-1);
            float4 v = *(const float4*)(ufea + (size_t)gr*D_ + c4*4);
            *(float4*)(pU + swz128(r, c4*4)) = v;
        }
        const int tx = tid & 15, ty = tid >> 4;
        uint32_t* sQw = (uint32_t*)(smc + B_SQ);
        #pragma unroll 1
        for (int h = 0; h < 4; ++h){
            __syncthreads();
            #pragma unroll
            for (int it = 0; it < 4; ++it){
                int idx = it*NT_ + tid;
                int lr = idx >> 5, c4 = idx & 31;
                float4 w = *(const float4*)(W + (size_t)(h*32+lr)*D_ + c4*4);
                *(float4*)(pW + swz128(lr, c4*4)) = w;
            }
            __syncthreads();
            float acc[4][2] = {};
            #pragma unroll
            for (int k4 = 0; k4 < 32; ++k4){
                float4 wv[2];
                #pragma unroll
                for (int j = 0; j < 2; ++j)
                    wv[j] = *(const float4*)(pW + swz128(tx*2+j, k4*4));
                #pragma unroll
                for (int i = 0; i < 4; ++i){
                    float4 uv = *(const float4*)(pU + swz128(ty*4+i, k4*4));
                    #pragma unroll
                    for (int j = 0; j < 2; ++j){
                        acc[i][j] += uv.x*wv[j].x; acc[i][j] += uv.y*wv[j].y;
                        acc[i][j] += uv.z*wv[j].z; acc[i][j] += uv.w*wv[j].w;
                    }
                }
            }
            const int c = h*32 + tx*2;
            const int ks = c >> 4, dd = c & 15;
            const int regb = (dd < 8) ? 0 : 2;
            const int tq = (dd & 7) >> 1;
            #pragma unroll
            for (int i = 0; i < 4; ++i){
                int r = ty*4 + i;
                int wmq = r >> 4, rw = r & 15, gq = rw & 7, hi = rw >> 3;
                uint32_t pk = h2u(acc[i][0] + bias[c], acc[i][1] + bias[c+1]);
                sQw[(((wmq*8 + ks)*32) + gq*4 + tq)*4 + regb + hi] = pk;
            }
        }
        __syncthreads();   // Q frags complete; staging regions now reusable
    }

    // ====== mainloop ======
    float oacc[8][4];
    #pragma unroll
    for (int i = 0; i < 8; ++i)
        #pragma unroll
        for (int j = 0; j < 4; ++j) oacc[i][j] = 0.f;
    float lacc0 = 0.f, lacc1 = 0.f;

    const int m0 = wm*16, n0 = wn*32, nd0 = wn*64;
    const int w8 = warp;
    const int cc2 = lane * 2;

    #pragma unroll 1
    for (int t = 0; t < TILES_; ++t){
        // ---- cp.async adj tile [64 x 64] -> sA[64][66] ----
        {
            const int tcol = t*64;
            #pragma unroll
            for (int itc = 0; itc < 8; ++itc){
                int rowa = itc*8 + w8;
                int gr = min(row0 + rowa, NU_-1);
                int lcc = tcol + cc2;
                const int* src = adj + (size_t)gr*NI_ + item0
                               + ((lcc < IPS_) ? lcc : 0);
                cpa8(sA_b + (uint32_t)((rowa*66 + cc2)*4), src);
            }
            CP_COMMIT();
        }
        __syncthreads();                       // O-mma(t-1) done with sBS/sBO/sP

        // ---- load I tile -> both fp16 B-fragment layouts ----
        #pragma unroll
        for (int p = 0; p < 4; ++p){
            const int j0 = (p*8 + w8)*2, j1 = j0 + 1;
            const int c  = lane;
            int gm0 = min(item0 + t*64 + j0, NI_-1);
            int gm1 = min(item0 + t*64 + j1, NI_-1);
            float4 v0 = *(const float4*)(inter + (size_t)gm0*D_ + c*4);
            float4 v1 = *(const float4*)(inter + (size_t)gm1*D_ + c*4);
            // S-layout: pairs along dims
            {
                const int ks = c >> 2;
                const int tg0 = (c & 1) << 1, bw = (c >> 1) & 1;
                const int jg = j0 >> 3;
                const int base = (jg*8 + ks)*32;
                int ph0 = (((j0&7)*4 + tg0)     ^ (ks<<2));
                int ph1 = (((j0&7)*4 + tg0 + 1) ^ (ks<<2));
                int ph2 = (((j1&7)*4 + tg0)     ^ (ks<<2));
                int ph3 = (((j1&7)*4 + tg0 + 1) ^ (ks<<2));
                sBS[(base + ph0)*2 + bw] = h2u(v0.x, v0.y);
                sBS[(base + ph1)*2 + bw] = h2u(v0.z, v0.w);
                sBS[(base + ph2)*2 + bw] = h2u(v1.x, v1.y);
                sBS[(base + ph3)*2 + bw] = h2u(v1.z, v1.w);
            }
            // O-layout: pairs along items
            {
                const int jj = j0 & 15;
                const int breg = jj >> 3, tgo = (jj & 7) >> 1;
                const int kso = j0 >> 4;
                const float f0[4] = {v0.x, v0.y, v0.z, v0.w};
                const float f1[4] = {v1.x, v1.y, v1.z, v1.w};
                #pragma unroll
                for (int i = 0; i < 4; ++i){
                    int d = 4*c + i;
                    int ng = d >> 3, gd = d & 7;
                    int ph = (gd*4 + tgo) ^ ((ng&7)<<2) ^ ((ng>>3)<<1);
                    sBO[((ng*4 + kso)*32 + ph)*2 + breg] = h2u(f0[i], f1[i]);
                }
            }
        }
        CP_WAIT0();
        __syncthreads();

        // ---- S = Q . I^T  (warp: 16 rows x 32 items) ----
        float sacc[4][4];
        #pragma unroll
        for (int nf = 0; nf < 4; ++nf)
            #pragma unroll
            for (int j = 0; j < 4; ++j) sacc[nf][j] = 0.f;
        #pragma unroll
        for (int ks = 0; ks < 8; ++ks){
            uint4 a4 = sQ[(wm*8 + ks)*32 + lane];
            const uint32_t A[4] = { a4.x, a4.y, a4.z, a4.w };
            #pragma unroll
            for (int nf = 0; nf < 4; ++nf){
                const int jg = wn*4 + nf;
                uint2 b2 = *(const uint2*)(sBS + ((jg*8 + ks)*32
                                                 + (lane ^ (ks<<2)))*2);
                const uint32_t B[2] = { b2.x, b2.y };
                mma16(sacc[nf], A, B);
            }
        }

        // ---- epilogue: scale, leaky2, mask, exp; P -> fp16 A-frags ----
        #pragma unroll
        for (int nf = 0; nf < 4; ++nf){
            const int c0 = n0 + nf*8 + 2*tig;
            const int lc = t*64 + c0;
            int2 a0 = make_int2(0,0), a1 = make_int2(0,0);
            if (lc < IPS_){
                a0 = *(const int2*)(sA + (m0+g)*66 + c0);
                a1 = *(const int2*)(sA + (m0+8+g)*66 + c0);
            }
            float v00 = sacc[nf][0]*SCALE_; v00 = fminf(v00, 2.f*v00);
            float v01 = sacc[nf][1]*SCALE_; v01 = fminf(v01, 2.f*v01);
            float v10 = sacc[nf][2]*SCALE_; v10 = fminf(v10, 2.f*v10);
            float v11 = sacc[nf][3]*SCALE_; v11 = fminf(v11, 2.f*v11);
            float p00 = (a0.x > 0) ? __expf(v00) : 0.f;
            float p01 = (a0.y > 0) ? __expf(v01) : 0.f;
            float p10 = (a1.x > 0) ? __expf(v10) : 0.f;
            float p11 = (a1.y > 0) ? __expf(v11) : 0.f;
            lacc0 += p00 + p01;
            lacc1 += p10 + p11;
            sacc[nf][0] = p00; sacc[nf][1] = p01;
            sacc[nf][2] = p10; sacc[nf][3] = p11;
        }
        #pragma unroll
        for (int kl = 0; kl < 2; ++kl){
            uint4 pk;
            pk.x = h2u(sacc[2*kl][0],   sacc[2*kl][1]);     // a0: row g, items lo
            pk.y = h2u(sacc[2*kl][2],   sacc[2*kl][3]);     // a1: row g+8, lo
            pk.z = h2u(sacc[2*kl+1][0], sacc[2*kl+1][1]);   // a2: row g, hi
            pk.w = h2u(sacc[2*kl+1][2], sacc[2*kl+1][3]);   // a3: row g+8, hi
            sP[(wm*4 + wn*2 + kl)*32 + lane] = pk;
        }
        __syncthreads();                       // P frags + (adj consumed)

        // ---- O += P . I  (warp: 16 rows x 64 dims) ----
        #pragma unroll
        for (int kso = 0; kso < 4; ++kso){
            uint4 a4 = sP[(wm*4 + kso)*32 + lane];
            const uint32_t A[4] = { a4.x, a4.y, a4.z, a4.w };
            #pragma unroll
            for (int nf = 0; nf < 8; ++nf){
                uint2 b2 = *(const uint2*)(sBO + (((wn*8 + nf)*4 + kso)*32
                                 + (lane ^ (nf<<2) ^ (wn<<1)))*2);
                const uint32_t B[2] = { b2.x, b2.y };
                mma16(oacc[nf], A, B);
            }
        }
    }

    // ---- l reduction ----
    lacc0 += __shfl_xor_sync(0xffffffffu, lacc0, 1);
    lacc0 += __shfl_xor_sync(0xffffffffu, lacc0, 2);
    lacc1 += __shfl_xor_sync(0xffffffffu, lacc1, 1);
    lacc1 += __shfl_xor_sync(0xffffffffu, lacc1, 2);
    if (tig == 0){
        sL[wn*64 + m0 + g]     = lacc0;
        sL[wn*64 + m0 + 8 + g] = lacc1;
    }
    __syncthreads();
    if (tid < BM_) g_lp[split][row0 + tid] = sL[tid] + sL[64 + tid];

    // ---- write unnormalized partial O ----
    {
        const int r0g = row0 + m0 + g, r1g = row0 + m0 + 8 + g;
        #pragma unroll
        for (int nf = 0; nf < 8; ++nf){
            const int dd = nd0 + nf*8 + 2*tig;
            if (r0g < NU_)
                *(float2*)(&g_op[split][(size_t)r0g*D_ + dd]) =
                    make_float2(oacc[nf][0], oacc[nf][1]);
            if (r1g < NU_)
                *(float2*)(&g_op[split][(size_t)r1g*D_ + dd]) =
                    make_float2(oacc[nf][2], oacc[nf][3]);
        }
    }
}

// ================= combine splits & normalize =================
__global__ __launch_bounds__(256) void gat_reduce(float* __restrict__ out)
{
    int idx = blockIdx.x*256 + threadIdx.x;
    int rr = idx >> 5, c4 = idx & 31;
    if (rr >= NU_) return;
    float l = g_lp[0][rr] + g_lp[1][rr];
    float4 a = *(const float4*)(&g_op[0][(size_t)rr*D_ + c4*4]);
    float4 b = *(const float4*)(&g_op[1][(size_t)rr*D_ + c4*4]);
    float inv = 1.0f / l;
    float4 o = make_float4((a.x+b.x)*inv, (a.y+b.y)*inv,
                           (a.z+b.z)*inv, (a.w+b.w)*inv);
    *(float4*)(out + (size_t)rr*D_ + c4*4) = o;
}

extern "C" void kernel_launch(void* const* d_in, const int* in_sizes, int n_in,
                              void* d_out, int out_size)
{
    const float* ufea  = (const float*)d_in[0];
    const float* inter = (const float*)d_in[1];
    const int*   adj   = (const int*)  d_in[2];
    const float* W     = (const float*)d_in[3];
    const float* bias  = (const float*)d_in[4];
    for (int i = 0; i < n_in; ++i) {
        int s = in_sizes[i];
        if      (s == NU_*D_)  ufea  = (const float*)d_in[i];
        else if (s == NI_*D_)  inter = (const float*)d_in[i];
        else if (s == NU_*NI_) adj   = (const int*)d_in[i];
        else if (s == D_*D_)   W     = (const float*)d_in[i];
        else if (s == D_)      bias  = (const float*)d_in[i];
    }

    cudaFuncSetAttribute(gat_main, cudaFuncAttributeMaxDynamicSharedMemorySize,
                         SMEM_B);

    dim3 grid(NRB_, NSPL_);                     // 157 x 2 = 314 CTAs
    gat_main<<<grid, NT_, SMEM_B>>>(ufea, inter, adj, W, bias);
    gat_reduce<<<(NU_*32 + 255)/256, 256>>>((float*)d_out);
}

// round 7
// speedup vs baseline: 4.6580x; 1.0036x over previous
#include <cuda_runtime.h>
#include <cuda_fp16.h>
#include <cstdint>

// GAT forward_user via mma.sync m16n8k16 fp16 (portable sm_103 HMMA path).
//   Per CTA (64 user rows, item-split s of 2):
//     prologue: Q = ufea@W^T+b exact fp32 -> fp16 A-fragments in smem
//     per 64-item tile: cp.async adj; I -> fp16 B-fragments (two layouts:
//       S-layout pairs dims, O-layout pairs items);
//       S = Q.I^T (fp32 acc); P = exp(mask(leaky2(S/sqrt(D)))); l += rowsum;
//       P -> fp16 A-fragments (direct from accumulator regs); O += P.I
//   reduce kernel: out = (sum_s O_s)/(sum_s l_s)

#define D_     128
#define NU_    10000
#define NI_    12000
#define BM_    64
#define NRB_   157
#define NRPAD_ (NRB_*BM_)
#define NSPL_  2
#define IPS_   6000
#define TILES_ 94
#define NT_    256
#define SCALE_ 0.08838834764831843f

__device__ float g_op[NSPL_][(size_t)NRPAD_*D_];
__device__ float g_lp[NSPL_][NRPAD_];

// ---- helpers ----
__device__ __forceinline__ uint32_t h2u(float a, float b){
    __half2 h = __floats2half2_rn(a, b);
    return *(uint32_t*)&h;
}
__device__ __forceinline__ void mma16(float* d, const uint32_t* a, const uint32_t* b){
    asm volatile("mma.sync.aligned.m16n8k16.row.col.f32.f16.f16.f32 "
        "{%0,%1,%2,%3}, {%4,%5,%6,%7}, {%8,%9}, {%0,%1,%2,%3};"
        : "+f"(d[0]), "+f"(d[1]), "+f"(d[2]), "+f"(d[3])
        : "r"(a[0]), "r"(a[1]), "r"(a[2]), "r"(a[3]), "r"(b[0]), "r"(b[1]));
}
__device__ __forceinline__ uint32_t smem_u32(const void* p){
    uint32_t a;
    asm("{ .reg .u64 t; cvta.to.shared.u64 t, %1; cvt.u32.u64 %0, t; }" : "=r"(a) : "l"(p));
    return a;
}
__device__ __forceinline__ void cpa8(uint32_t dst, const void* src){
    asm volatile("cp.async.ca.shared.global [%0], [%1], 8;" :: "r"(dst), "l"(src));
}
#define CP_COMMIT() asm volatile("cp.async.commit_group;" ::: "memory")
#define CP_WAIT0()  asm volatile("cp.async.wait_group 0;" ::: "memory")

__device__ __forceinline__ int swz128(int r, int c){
    return (r<<7) | ((((c>>2) ^ (r&7)) << 2) | (c&3));
}

// smem byte offsets
#define B_SQ   0        // Q A-frag:  [wm*8+ks:32][lane32][uint4]      16384
#define B_SBS  16384    // I B-frag S:[jg8][ks8][lane32][uint2]        16384
#define B_SBO  32768    // I B-frag O:[ng16][ks4][lane32][uint2]       16384
#define B_SP   49152    // P A-frag:  [wm*4+kso:16][lane32][uint4]      8192
#define B_ADJ  57344    // adj ints [64][66]                           16896
#define B_L    74240    // 128 floats                                    512
#define SMEM_B 74752

__global__ __launch_bounds__(NT_, 2)
void gat_main(const float* __restrict__ ufea, const float* __restrict__ inter,
              const int* __restrict__ adj, const float* __restrict__ W,
              const float* __restrict__ bias)
{
    extern __shared__ char smc[];
    uint4*    sQ  = (uint4*)(smc + B_SQ);
    uint32_t* sBS = (uint32_t*)(smc + B_SBS);
    uint32_t* sBO = (uint32_t*)(smc + B_SBO);
    uint4*    sP  = (uint4*)(smc + B_SP);
    int*      sA  = (int*)(smc + B_ADJ);
    float*    sL  = (float*)(smc + B_L);
    const uint32_t sA_b = smem_u32(sA);

    const int tid  = threadIdx.x;
    const int lane = tid & 31, warp = tid >> 5;
    const int g    = lane >> 2, tig = lane & 3;
    const int wm   = warp >> 1, wn  = warp & 1;
    const int row0  = blockIdx.x * BM_;
    const int split = blockIdx.y;
    const int item0 = split * IPS_;

    // ====== prologue: Q = ufea @ W^T + b (fp32 exact) -> fp16 A-frags ======
    {
        float* pU = (float*)(smc + B_SBS);     // 32KB staging (SBS+SBO)
        float* pW = (float*)(smc + B_SP);      // 16KB staging (SP+ADJ head)
        #pragma unroll
        for (int it = 0; it < 8; ++it){
            int idx = it*NT_ + tid;
            int r = idx >> 5, c4 = idx & 31;
            int gr = min(row0 + r, NU_-1);
            float4 v = *(const float4*)(ufea + (size_t)gr*D_ + c4*4);
            *(float4*)(pU + swz128(r, c4*4)) = v;
        }
        const int tx = tid & 15, ty = tid >> 4;
        uint32_t* sQw = (uint32_t*)(smc + B_SQ);
        #pragma unroll 1
        for (int h = 0; h < 4; ++h){
            __syncthreads();
            #pragma unroll
            for (int it = 0; it < 4; ++it){
                int idx = it*NT_ + tid;
                int lr = idx >> 5, c4 = idx & 31;
                float4 w = *(const float4*)(W + (size_t)(h*32+lr)*D_ + c4*4);
                *(float4*)(pW + swz128(lr, c4*4)) = w;
            }
            __syncthreads();
            float acc[4][2] = {};
            #pragma unroll
            for (int k4 = 0; k4 < 32; ++k4){
                float4 wv[2];
                #pragma unroll
                for (int j = 0; j < 2; ++j)
                    wv[j] = *(const float4*)(pW + swz128(tx*2+j, k4*4));
                #pragma unroll
                for (int i = 0; i < 4; ++i){
                    float4 uv = *(const float4*)(pU + swz128(ty*4+i, k4*4));
                    #pragma unroll
                    for (int j = 0; j < 2; ++j){
                        acc[i][j] += uv.x*wv[j].x; acc[i][j] += uv.y*wv[j].y;
                        acc[i][j] += uv.z*wv[j].z; acc[i][j] += uv.w*wv[j].w;
                    }
                }
            }
            const int c = h*32 + tx*2;
            const int ks = c >> 4, dd = c & 15;
            const int regb = (dd < 8) ? 0 : 2;
            const int tq = (dd & 7) >> 1;
            #pragma unroll
            for (int i = 0; i < 4; ++i){
                int r = ty*4 + i;
                int wmq = r >> 4, rw = r & 15, gq = rw & 7, hi = rw >> 3;
                uint32_t pk = h2u(acc[i][0] + bias[c], acc[i][1] + bias[c+1]);
                sQw[(((wmq*8 + ks)*32) + gq*4 + tq)*4 + regb + hi] = pk;
            }
        }
        __syncthreads();   // Q frags complete; staging regions now reusable
    }

    // ====== mainloop ======
    float oacc[8][4];
    #pragma unroll
    for (int i = 0; i < 8; ++i)
        #pragma unroll
        for (int j = 0; j < 4; ++j) oacc[i][j] = 0.f;
    float lacc0 = 0.f, lacc1 = 0.f;

    const int m0 = wm*16, n0 = wn*32, nd0 = wn*64;
    const int w8 = warp;
    const int cc2 = lane * 2;

    #pragma unroll 1
    for (int t = 0; t < TILES_; ++t){
        // ---- cp.async adj tile [64 x 64] -> sA[64][66] ----
        {
            const int tcol = t*64;
            #pragma unroll
            for (int itc = 0; itc < 8; ++itc){
                int rowa = itc*8 + w8;
                int gr = min(row0 + rowa, NU_-1);
                int lcc = tcol + cc2;
                const int* src = adj + (size_t)gr*NI_ + item0
                               + ((lcc < IPS_) ? lcc : 0);
                cpa8(sA_b + (uint32_t)((rowa*66 + cc2)*4), src);
            }
            CP_COMMIT();
        }
        __syncthreads();                       // O-mma(t-1) done with sBS/sBO/sP

        // ---- load I tile -> both fp16 B-fragment layouts ----
        #pragma unroll
        for (int p = 0; p < 4; ++p){
            const int j0 = (p*8 + w8)*2, j1 = j0 + 1;
            const int c  = lane;
            int gm0 = min(item0 + t*64 + j0, NI_-1);
            int gm1 = min(item0 + t*64 + j1, NI_-1);
            float4 v0 = *(const float4*)(inter + (size_t)gm0*D_ + c*4);
            float4 v1 = *(const float4*)(inter + (size_t)gm1*D_ + c*4);
            // S-layout: pairs along dims
            {
                const int ks = c >> 2;
                const int tg0 = (c & 1) << 1, bw = (c >> 1) & 1;
                const int jg = j0 >> 3;
                const int base = (jg*8 + ks)*32;
                int ph0 = (((j0&7)*4 + tg0)     ^ (ks<<2));
                int ph1 = (((j0&7)*4 + tg0 + 1) ^ (ks<<2));
                int ph2 = (((j1&7)*4 + tg0)     ^ (ks<<2));
                int ph3 = (((j1&7)*4 + tg0 + 1) ^ (ks<<2));
                sBS[(base + ph0)*2 + bw] = h2u(v0.x, v0.y);
                sBS[(base + ph1)*2 + bw] = h2u(v0.z, v0.w);
                sBS[(base + ph2)*2 + bw] = h2u(v1.x, v1.y);
                sBS[(base + ph3)*2 + bw] = h2u(v1.z, v1.w);
            }
            // O-layout: pairs along items
            {
                const int jj = j0 & 15;
                const int breg = jj >> 3, tgo = (jj & 7) >> 1;
                const int kso = j0 >> 4;
                const float f0[4] = {v0.x, v0.y, v0.z, v0.w};
                const float f1[4] = {v1.x, v1.y, v1.z, v1.w};
                #pragma unroll
                for (int i = 0; i < 4; ++i){
                    int d = 4*c + i;
                    int ng = d >> 3, gd = d & 7;
                    int ph = (gd*4 + tgo) ^ ((ng&7)<<2) ^ ((ng>>3)<<1);
                    sBO[((ng*4 + kso)*32 + ph)*2 + breg] = h2u(f0[i], f1[i]);
                }
            }
        }
        CP_WAIT0();
        __syncthreads();

        // ---- S = Q . I^T  (warp: 16 rows x 32 items) ----
        float sacc[4][4];
        #pragma unroll
        for (int nf = 0; nf < 4; ++nf)
            #pragma unroll
            for (int j = 0; j < 4; ++j) sacc[nf][j] = 0.f;
        #pragma unroll
        for (int ks = 0; ks < 8; ++ks){
            uint4 a4 = sQ[(wm*8 + ks)*32 + lane];
            const uint32_t A[4] = { a4.x, a4.y, a4.z, a4.w };
            #pragma unroll
            for (int nf = 0; nf < 4; ++nf){
                const int jg = wn*4 + nf;
                uint2 b2 = *(const uint2*)(sBS + ((jg*8 + ks)*32
                                                 + (lane ^ (ks<<2)))*2);
                const uint32_t B[2] = { b2.x, b2.y };
                mma16(sacc[nf], A, B);
            }
        }

        // ---- epilogue: scale, leaky2, mask, exp; P -> fp16 A-frags ----
        #pragma unroll
        for (int nf = 0; nf < 4; ++nf){
            const int c0 = n0 + nf*8 + 2*tig;
            const int lc = t*64 + c0;
            int2 a0 = make_int2(0,0), a1 = make_int2(0,0);
            if (lc < IPS_){
                a0 = *(const int2*)(sA + (m0+g)*66 + c0);
                a1 = *(const int2*)(sA + (m0+8+g)*66 + c0);
            }
            float v00 = sacc[nf][0]*SCALE_; v00 = fminf(v00, 2.f*v00);
            float v01 = sacc[nf][1]*SCALE_; v01 = fminf(v01, 2.f*v01);
            float v10 = sacc[nf][2]*SCALE_; v10 = fminf(v10, 2.f*v10);
            float v11 = sacc[nf][3]*SCALE_; v11 = fminf(v11, 2.f*v11);
            float p00 = (a0.x > 0) ? __expf(v00) : 0.f;
            float p01 = (a0.y > 0) ? __expf(v01) : 0.f;
            float p10 = (a1.x > 0) ? __expf(v10) : 0.f;
            float p11 = (a1.y > 0) ? __expf(v11) : 0.f;
            lacc0 += p00 + p01;
            lacc1 += p10 + p11;
            sacc[nf][0] = p00; sacc[nf][1] = p01;
            sacc[nf][2] = p10; sacc[nf][3] = p11;
        }
        #pragma unroll
        for (int kl = 0; kl < 2; ++kl){
            uint4 pk;
            pk.x = h2u(sacc[2*kl][0],   sacc[2*kl][1]);     // a0: row g, items lo
            pk.y = h2u(sacc[2*kl][2],   sacc[2*kl][3]);     // a1: row g+8, lo
            pk.z = h2u(sacc[2*kl+1][0], sacc[2*kl+1][1]);   // a2: row g, hi
            pk.w = h2u(sacc[2*kl+1][2], sacc[2*kl+1][3]);   // a3: row g+8, hi
            sP[(wm*4 + wn*2 + kl)*32 + lane] = pk;
        }
        __syncthreads();                       // P frags + (adj consumed)

        // ---- O += P . I  (warp: 16 rows x 64 dims) ----
        #pragma unroll
        for (int kso = 0; kso < 4; ++kso){
            uint4 a4 = sP[(wm*4 + kso)*32 + lane];
            const uint32_t A[4] = { a4.x, a4.y, a4.z, a4.w };
            #pragma unroll
            for (int nf = 0; nf < 8; ++nf){
                uint2 b2 = *(const uint2*)(sBO + (((wn*8 + nf)*4 + kso)*32
                                 + (lane ^ (nf<<2) ^ (wn<<1)))*2);
                const uint32_t B[2] = { b2.x, b2.y };
                mma16(oacc[nf], A, B);
            }
        }
    }

    // ---- l reduction ----
    lacc0 += __shfl_xor_sync(0xffffffffu, lacc0, 1);
    lacc0 += __shfl_xor_sync(0xffffffffu, lacc0, 2);
    lacc1 += __shfl_xor_sync(0xffffffffu, lacc1, 1);
    lacc1 += __shfl_xor_sync(0xffffffffu, lacc1, 2);
    if (tig == 0){
        sL[wn*64 + m0 + g]     = lacc0;
        sL[wn*64 + m0 + 8 + g] = lacc1;
    }
    __syncthreads();
    if (tid < BM_) g_lp[split][row0 + tid] = sL[tid] + sL[64 + tid];

    // ---- write unnormalized partial O ----
    {
        const int r0g = row0 + m0 + g, r1g = row0 + m0 + 8 + g;
        #pragma unroll
        for (int nf = 0; nf < 8; ++nf){
            const int dd = nd0 + nf*8 + 2*tig;
            if (r0g < NU_)
                *(float2*)(&g_op[split][(size_t)r0g*D_ + dd]) =
                    make_float2(oacc[nf][0], oacc[nf][1]);
            if (r1g < NU_)
                *(float2*)(&g_op[split][(size_t)r1g*D_ + dd]) =
                    make_float2(oacc[nf][2], oacc[nf][3]);
        }
    }
}

// ================= combine splits & normalize =================
__global__ __launch_bounds__(256) void gat_reduce(float* __restrict__ out)
{
    int idx = blockIdx.x*256 + threadIdx.x;
    int rr = idx >> 5, c4 = idx & 31;
    if (rr >= NU_) return;
    float l = g_lp[0][rr] + g_lp[1][rr];
    float4 a = *(const float4*)(&g_op[0][(size_t)rr*D_ + c4*4]);
    float4 b = *(const float4*)(&g_op[1][(size_t)rr*D_ + c4*4]);
    float inv = 1.0f / l;
    float4 o = make_float4((a.x+b.x)*inv, (a.y+b.y)*inv,
                           (a.z+b.z)*inv, (a.w+b.w)*inv);
    *(float4*)(out + (size_t)rr*D_ + c4*4) = o;
}

extern "C" void kernel_launch(void* const* d_in, const int* in_sizes, int n_in,
                              void* d_out, int out_size)
{
    const float* ufea  = (const float*)d_in[0];
    const float* inter = (const float*)d_in[1];
    const int*   adj   = (const int*)  d_in[2];
    const float* W     = (const float*)d_in[3];
    const float* bias  = (const float*)d_in[4];
    for (int i = 0; i < n_in; ++i) {
        int s = in_sizes[i];
        if      (s == NU_*D_)  ufea  = (const float*)d_in[i];
        else if (s == NI_*D_)  inter = (const float*)d_in[i];
        else if (s == NU_*NI_) adj   = (const int*)d_in[i];
        else if (s == D_*D_)   W     = (const float*)d_in[i];
        else if (s == D_)      bias  = (const float*)d_in[i];
    }

    cudaFuncSetAttribute(gat_main, cudaFuncAttributeMaxDynamicSharedMemorySize,
                         SMEM_B);

    dim3 grid(NRB_, NSPL_);                     // 157 x 2 = 314 CTAs
    gat_main<<<grid, NT_, SMEM_B>>>(ufea, inter, adj, W, bias);
    gat_reduce<<<(NU_*32 + 255)/256, 256>>>((float*)d_out);
}

// round 8
// speedup vs baseline: 5.7320x; 1.2306x over previous
#include <cuda_runtime.h>
#include <cuda_fp16.h>
#include <cstdint>

// GAT forward_user: mma.sync m16n8k16 fp16, single-copy I tile via ldmatrix,
// double-buffered I+adj, one __syncthreads + one named barrier per tile.
//   S = Q.I^T  (B-frags: ldmatrix non-trans, k = dims)
//   P = exp(mask(leaky2(S/sqrt(D))));  l += rowsum(P)   [exp(-9e15)=0]
//   O += P.I   (B-frags: ldmatrix.trans, k = items)
// split-2 over items; reduce kernel normalizes.

#define D_     128
#define NU_    10000
#define NI_    12000
#define BM_    64
#define NRB_   157
#define NRPAD_ (NRB_*BM_)
#define NSPL_  2
#define IPS_   6000
#define TILES_ 94
#define NT_    256
#define SCALE_ 0.08838834764831843f

__device__ float g_op[NSPL_][(size_t)NRPAD_*D_];
__device__ float g_lp[NSPL_][NRPAD_];

// ---- helpers ----
__device__ __forceinline__ uint32_t h2u(float a, float b){
    __half2 h = __floats2half2_rn(a, b);
    return *(uint32_t*)&h;
}
__device__ __forceinline__ void mma16(float* d, const uint32_t* a, const uint32_t* b){
    asm volatile("mma.sync.aligned.m16n8k16.row.col.f32.f16.f16.f32 "
        "{%0,%1,%2,%3}, {%4,%5,%6,%7}, {%8,%9}, {%0,%1,%2,%3};"
        : "+f"(d[0]), "+f"(d[1]), "+f"(d[2]), "+f"(d[3])
        : "r"(a[0]), "r"(a[1]), "r"(a[2]), "r"(a[3]), "r"(b[0]), "r"(b[1]));
}
__device__ __forceinline__ void ldsm4(uint32_t* r, uint32_t a){
    asm volatile("ldmatrix.sync.aligned.m8n8.x4.shared.b16 {%0,%1,%2,%3}, [%4];"
        : "=r"(r[0]), "=r"(r[1]), "=r"(r[2]), "=r"(r[3]) : "r"(a));
}
__device__ __forceinline__ void ldsm4t(uint32_t* r, uint32_t a){
    asm volatile("ldmatrix.sync.aligned.m8n8.x4.trans.shared.b16 {%0,%1,%2,%3}, [%4];"
        : "=r"(r[0]), "=r"(r[1]), "=r"(r[2]), "=r"(r[3]) : "r"(a));
}
__device__ __forceinline__ uint32_t smem_u32(const void* p){
    uint32_t a;
    asm("{ .reg .u64 t; cvta.to.shared.u64 t, %1; cvt.u32.u64 %0, t; }" : "=r"(a) : "l"(p));
    return a;
}
__device__ __forceinline__ void cpa8(uint32_t dst, const void* src){
    asm volatile("cp.async.ca.shared.global [%0], [%1], 8;" :: "r"(dst), "l"(src));
}
#define CP_COMMIT() asm volatile("cp.async.commit_group;" ::: "memory")
#define CP_WAIT1()  asm volatile("cp.async.wait_group 1;" ::: "memory")
#define BARW(id)    asm volatile("bar.sync %0, %1;" :: "r"(id), "r"(64) : "memory")

__device__ __forceinline__ int swz128(int r, int c){
    return (r<<7) | ((((c>>2) ^ (r&7)) << 2) | (c&3));
}

// smem byte offsets
#define B_SQ   0         // Q A-frag: [wm*8+ks][lane] uint4          16384
#define B_I0   16384     // I fp16 [64 items][16 gran x 16B] swz     16384
#define B_I1   32768     //   (double buffer)                        16384
#define B_SP   49152     // P A-frag: [wm*4+kso][lane] uint4          8192
#define B_ADJ  57344     // adj ints [2][64][66]                     33792
#define ADJ_I  4224      // ints per adj buffer
#define B_L    91136     // 128 floats
#define SMEM_B 91648

// store one item row's 4 dims (lane-local) as fp16 into I buffer
#define STORE_I(bufoff, j, v) do{ \
    *(uint2*)(smc + (bufoff) + (j)*256 + ((((lane>>1) ^ ((j)&7)))<<4) \
              + ((lane&1)<<3)) = make_uint2(h2u((v).x,(v).y), h2u((v).z,(v).w)); \
}while(0)

__global__ __launch_bounds__(NT_, 2)
void gat_main(const float* __restrict__ ufea, const float* __restrict__ inter,
              const int* __restrict__ adj, const float* __restrict__ W,
              const float* __restrict__ bias)
{
    extern __shared__ char smc[];
    int*   sA = (int*)(smc + B_ADJ);
    float* sL = (float*)(smc + B_L);
    const uint32_t smb  = smem_u32(smc);
    const uint32_t sA_b = smb + B_ADJ;

    const int tid  = threadIdx.x;
    const int lane = tid & 31, warp = tid >> 5;
    const int g    = lane >> 2, tig = lane & 3;
    const int wm   = warp >> 1, wn  = warp & 1;
    const int row0  = blockIdx.x * BM_;
    const int split = blockIdx.y;
    const int item0 = split * IPS_;

    // ====== prologue: Q = ufea @ W^T + b (fp32 exact) -> fp16 A-frags ======
    {
        float* pU = (float*)(smc + B_I0);       // 32KB staging (I0+I1)
        float* pW = (float*)(smc + B_ADJ);      // 16KB staging (adj area)
        #pragma unroll
        for (int it = 0; it < 8; ++it){
            int idx = it*NT_ + tid;
            int r = idx >> 5, c4 = idx & 31;
            int gr = min(row0 + r, NU_-1);
            float4 v = *(const float4*)(ufea + (size_t)gr*D_ + c4*4);
            *(float4*)(pU + swz128(r, c4*4)) = v;
        }
        const int tx = tid & 15, ty = tid >> 4;
        uint32_t* sQw = (uint32_t*)(smc + B_SQ);
        #pragma unroll 1
        for (int h = 0; h < 4; ++h){
            __syncthreads();
            #pragma unroll
            for (int it = 0; it < 4; ++it){
                int idx = it*NT_ + tid;
                int lr = idx >> 5, c4 = idx & 31;
                float4 w = *(const float4*)(W + (size_t)(h*32+lr)*D_ + c4*4);
                *(float4*)(pW + swz128(lr, c4*4)) = w;
            }
            __syncthreads();
            float acc[4][2] = {};
            #pragma unroll
            for (int k4 = 0; k4 < 32; ++k4){
                float4 wv[2];
                #pragma unroll
                for (int j = 0; j < 2; ++j)
                    wv[j] = *(const float4*)(pW + swz128(tx*2+j, k4*4));
                #pragma unroll
                for (int i = 0; i < 4; ++i){
                    float4 uv = *(const float4*)(pU + swz128(ty*4+i, k4*4));
                    #pragma unroll
                    for (int j = 0; j < 2; ++j){
                        acc[i][j] += uv.x*wv[j].x; acc[i][j] += uv.y*wv[j].y;
                        acc[i][j] += uv.z*wv[j].z; acc[i][j] += uv.w*wv[j].w;
                    }
                }
            }
            const int c = h*32 + tx*2;
            const int ks = c >> 4, dd = c & 15;
            const int regb = (dd < 8) ? 0 : 2;
            const int tq = (dd & 7) >> 1;
            #pragma unroll
            for (int i = 0; i < 4; ++i){
                int r = ty*4 + i;
                int wmq = r >> 4, rw = r & 15, gq = rw & 7, hi = rw >> 3;
                uint32_t pk = h2u(acc[i][0] + bias[c], acc[i][1] + bias[c+1]);
                sQw[(((wmq*8 + ks)*32) + gq*4 + tq)*4 + regb + hi] = pk;
            }
        }
        __syncthreads();
    }

    // ====== pipeline prologue: adj(0) cp.async, I(0) -> buf0 ======
    const int cc2 = lane * 2;
    {
        #pragma unroll
        for (int itc = 0; itc < 8; ++itc){
            int rowa = itc*8 + warp;
            int gr = min(row0 + rowa, NU_-1);
            int lcc = cc2;                       // tile 0 cols
            const int* src = adj + (size_t)gr*NI_ + item0 + ((lcc < IPS_) ? lcc : 0);
            cpa8(sA_b + (uint32_t)((rowa*66 + cc2)*4), src);
        }
        CP_COMMIT();
        #pragma unroll
        for (int p = 0; p < 4; ++p){
            int j0 = (p*8 + warp)*2;
            int gm0 = min(item0 + j0,     NI_-1);
            int gm1 = min(item0 + j0 + 1, NI_-1);
            float4 v0 = *(const float4*)(inter + (size_t)gm0*D_ + lane*4);
            float4 v1 = *(const float4*)(inter + (size_t)gm1*D_ + lane*4);
            STORE_I(B_I0, j0,   v0);
            STORE_I(B_I0, j0+1, v1);
        }
    }
    __syncthreads();

    // ====== mainloop ======
    float oacc[8][4];
    #pragma unroll
    for (int i = 0; i < 8; ++i)
        #pragma unroll
        for (int j = 0; j < 4; ++j) oacc[i][j] = 0.f;
    float lacc0 = 0.f, lacc1 = 0.f;

    const int m0 = wm*16, n0 = wn*32, nd0 = wn*64;
    const int laneM = lane & 7;
    // S ldmatrix row/chunk decomposition: m0,m1 = chunk+0/+1 ; m2,m3 = rows+8
    const int jloS = ((lane>>4)&1) << 3, chS = (lane>>3)&1;
    // O (trans): m0,m1 = rows+0/+8 ; m2,m3 = chunk+1
    const int jloO = ((lane>>3)&1) << 3, chO = (lane>>4)&1;
    const int jS0 = n0 + jloS + laneM,  jS1 = jS0 + 16;
    const uint32_t rbS0 = (uint32_t)(jS0*256), rbS1 = (uint32_t)(jS1*256);
    const int j7S0 = jS0 & 7, j7S1 = jS1 & 7;

    #pragma unroll 1
    for (int t = 0; t < TILES_; ++t){
        const int cur = t & 1, nxt = cur ^ 1;
        const uint32_t ibase = smb + (cur ? B_I1 : B_I0);

        // ---- adj(t+1) cp.async into other buffer ----
        if (t+1 < TILES_){
            const int tcol = (t+1)*64;
            #pragma unroll
            for (int itc = 0; itc < 8; ++itc){
                int rowa = itc*8 + warp;
                int gr = min(row0 + rowa, NU_-1);
                int lcc = tcol + cc2;
                const int* src = adj + (size_t)gr*NI_ + item0 + ((lcc < IPS_) ? lcc : 0);
                cpa8(sA_b + (uint32_t)((nxt*ADJ_I + rowa*66 + cc2)*4), src);
            }
        }
        CP_COMMIT();

        // ---- I(t+1) gmem prefetch (first half) ----
        float4 pv0[4];
        if (t+1 < TILES_){
            #pragma unroll
            for (int p = 0; p < 2; ++p){
                int j0 = (p*8 + warp)*2;
                int gm0 = min(item0 + (t+1)*64 + j0,     NI_-1);
                int gm1 = min(item0 + (t+1)*64 + j0 + 1, NI_-1);
                pv0[p*2]   = *(const float4*)(inter + (size_t)gm0*D_ + lane*4);
                pv0[p*2+1] = *(const float4*)(inter + (size_t)gm1*D_ + lane*4);
            }
        }

        // ---- S = Q . I^T  (16 rows x 32 items per warp) ----
        float sacc[4][4];
        #pragma unroll
        for (int nf = 0; nf < 4; ++nf)
            #pragma unroll
            for (int j = 0; j < 4; ++j) sacc[nf][j] = 0.f;
        #pragma unroll
        for (int ks = 0; ks < 8; ++ks){
            uint4 a4 = *(const uint4*)(smc + B_SQ + (((wm*8+ks)*32 + lane)<<4));
            const uint32_t A[4] = { a4.x, a4.y, a4.z, a4.w };
            uint32_t r[4];
            ldsm4(r, ibase + rbS0 + (uint32_t)((((2*ks + chS) ^ j7S0))<<4));
            mma16(sacc[0], A, r);
            mma16(sacc[1], A, r+2);
            ldsm4(r, ibase + rbS1 + (uint32_t)((((2*ks + chS) ^ j7S1))<<4));
            mma16(sacc[2], A, r);
            mma16(sacc[3], A, r+2);
        }

        // ---- I(t+1) gmem prefetch (second half) ----
        float4 pv1[4];
        if (t+1 < TILES_){
            #pragma unroll
            for (int p = 2; p < 4; ++p){
                int j0 = (p*8 + warp)*2;
                int gm0 = min(item0 + (t+1)*64 + j0,     NI_-1);
                int gm1 = min(item0 + (t+1)*64 + j0 + 1, NI_-1);
                pv1[(p-2)*2]   = *(const float4*)(inter + (size_t)gm0*D_ + lane*4);
                pv1[(p-2)*2+1] = *(const float4*)(inter + (size_t)gm1*D_ + lane*4);
            }
        }

        CP_WAIT1();                              // adj(t) landed

        // ---- epilogue: scale, leaky2, mask, exp; P -> fp16 A-frags ----
        const int* sAc = sA + cur*ADJ_I;
        #pragma unroll
        for (int nf = 0; nf < 4; ++nf){
            const int c0 = n0 + nf*8 + 2*tig;
            const int lc = t*64 + c0;
            int2 a0 = make_int2(0,0), a1 = make_int2(0,0);
            if (lc < IPS_){
                a0 = *(const int2*)(sAc + (m0+g)*66 + c0);
                a1 = *(const int2*)(sAc + (m0+8+g)*66 + c0);
            }
            float v00 = sacc[nf][0]*SCALE_; v00 = fminf(v00, 2.f*v00);
            float v01 = sacc[nf][1]*SCALE_; v01 = fminf(v01, 2.f*v01);
            float v10 = sacc[nf][2]*SCALE_; v10 = fminf(v10, 2.f*v10);
            float v11 = sacc[nf][3]*SCALE_; v11 = fminf(v11, 2.f*v11);
            float p00 = (a0.x > 0) ? __expf(v00) : 0.f;
            float p01 = (a0.y > 0) ? __expf(v01) : 0.f;
            float p10 = (a1.x > 0) ? __expf(v10) : 0.f;
            float p11 = (a1.y > 0) ? __expf(v11) : 0.f;
            lacc0 += p00 + p01;
            lacc1 += p10 + p11;
            sacc[nf][0] = p00; sacc[nf][1] = p01;
            sacc[nf][2] = p10; sacc[nf][3] = p11;
        }
        #pragma unroll
        for (int kl = 0; kl < 2; ++kl){
            uint4 pk;
            pk.x = h2u(sacc[2*kl][0],   sacc[2*kl][1]);
            pk.y = h2u(sacc[2*kl][2],   sacc[2*kl][3]);
            pk.z = h2u(sacc[2*kl+1][0], sacc[2*kl+1][1]);
            pk.w = h2u(sacc[2*kl+1][2], sacc[2*kl+1][3]);
            *(uint4*)(smc + B_SP + (((wm*4 + wn*2 + kl)*32 + lane)<<4)) = pk;
        }
        BARW(1 + wm);                            // P visible within wm-pair

        // ---- O += P . I  (16 rows x 64 dims per warp) ----
        #pragma unroll
        for (int kso = 0; kso < 4; ++kso){
            uint4 a4 = *(const uint4*)(smc + B_SP + (((wm*4+kso)*32 + lane)<<4));
            const uint32_t A[4] = { a4.x, a4.y, a4.z, a4.w };
            const int j = kso*16 + jloO + laneM;
            const uint32_t rb = ibase + (uint32_t)(j*256);
            const int j7 = j & 7;
            #pragma unroll
            for (int nh = 0; nh < 4; ++nh){
                uint32_t r[4];
                ldsm4t(r, rb + (uint32_t)(((((nd0>>3) + nh*2 + chO) ^ j7))<<4));
                mma16(oacc[nh*2],   A, r);
                mma16(oacc[nh*2+1], A, r+2);
            }
        }

        // ---- store I(t+1) into other buffer ----
        if (t+1 < TILES_){
            const int joff0 = warp*2, joff1 = 16 + warp*2,
                      joff2 = 32 + warp*2, joff3 = 48 + warp*2;
            STORE_I((nxt? B_I1 : B_I0), joff0,   pv0[0]);
            STORE_I((nxt? B_I1 : B_I0), joff0+1, pv0[1]);
            STORE_I((nxt? B_I1 : B_I0), joff1,   pv0[2]);
            STORE_I((nxt? B_I1 : B_I0), joff1+1, pv0[3]);
            STORE_I((nxt? B_I1 : B_I0), joff2,   pv1[0]);
            STORE_I((nxt? B_I1 : B_I0), joff2+1, pv1[1]);
            STORE_I((nxt? B_I1 : B_I0), joff3,   pv1[2]);
            STORE_I((nxt? B_I1 : B_I0), joff3+1, pv1[3]);
        }
        __syncthreads();                         // publish buffers
    }

    // ---- l reduction ----
    lacc0 += __shfl_xor_sync(0xffffffffu, lacc0, 1);
    lacc0 += __shfl_xor_sync(0xffffffffu, lacc0, 2);
    lacc1 += __shfl_xor_sync(0xffffffffu, lacc1, 1);
    lacc1 += __shfl_xor_sync(0xffffffffu, lacc1, 2);
    if (tig == 0){
        sL[wn*64 + m0 + g]     = lacc0;
        sL[wn*64 + m0 + 8 + g] = lacc1;
    }
    __syncthreads();
    if (tid < BM_) g_lp[split][row0 + tid] = sL[tid] + sL[64 + tid];

    // ---- write unnormalized partial O ----
    {
        const int r0g = row0 + m0 + g, r1g = row0 + m0 + 8 + g;
        #pragma unroll
        for (int nf = 0; nf < 8; ++nf){
            const int dd = nd0 + nf*8 + 2*tig;
            if (r0g < NU_)
                *(float2*)(&g_op[split][(size_t)r0g*D_ + dd]) =
                    make_float2(oacc[nf][0], oacc[nf][1]);
            if (r1g < NU_)
                *(float2*)(&g_op[split][(size_t)r1g*D_ + dd]) =
                    make_float2(oacc[nf][2], oacc[nf][3]);
        }
    }
}

// ================= combine splits & normalize =================
__global__ __launch_bounds__(256) void gat_reduce(float* __restrict__ out)
{
    int idx = blockIdx.x*256 + threadIdx.x;
    int rr = idx >> 5, c4 = idx & 31;
    if (rr >= NU_) return;
    float l = g_lp[0][rr] + g_lp[1][rr];
    float4 a = *(const float4*)(&g_op[0][(size_t)rr*D_ + c4*4]);
    float4 b = *(const float4*)(&g_op[1][(size_t)rr*D_ + c4*4]);
    float inv = 1.0f / l;
    float4 o = make_float4((a.x+b.x)*inv, (a.y+b.y)*inv,
                           (a.z+b.z)*inv, (a.w+b.w)*inv);
    *(float4*)(out + (size_t)rr*D_ + c4*4) = o;
}

extern "C" void kernel_launch(void* const* d_in, const int* in_sizes, int n_in,
                              void* d_out, int out_size)
{
    const float* ufea  = (const float*)d_in[0];
    const float* inter = (const float*)d_in[1];
    const int*   adj   = (const int*)  d_in[2];
    const float* W     = (const float*)d_in[3];
    const float* bias  = (const float*)d_in[4];
    for (int i = 0; i < n_in; ++i) {
        int s = in_sizes[i];
        if      (s == NU_*D_)  ufea  = (const float*)d_in[i];
        else if (s == NI_*D_)  inter = (const float*)d_in[i];
        else if (s == NU_*NI_) adj   = (const int*)d_in[i];
        else if (s == D_*D_)   W     = (const float*)d_in[i];
        else if (s == D_)      bias  = (const float*)d_in[i];
    }

    cudaFuncSetAttribute(gat_main, cudaFuncAttributeMaxDynamicSharedMemorySize,
                         SMEM_B);

    dim3 grid(NRB_, NSPL_);                      // 157 x 2 = 314 CTAs
    gat_main<<<grid, NT_, SMEM_B>>>(ufea, inter, adj, W, bias);
    gat_reduce<<<(NU_*32 + 255)/256, 256>>>((float*)d_out);
}